// round 8
// baseline (speedup 1.0000x reference)
#include <cuda_runtime.h>
#include <cuda_bf16.h>
#include <cstdint>

#define BB 16
#define NN 576
#define DD 1024
#define HH 16
#define HD 64

// ---------------- scratch (static device globals; no allocation) ----------------
__device__ float g_qk[(long)BB * NN * 2 * DD];        // [B,N,2D]
__device__ float g_v[(long)BB * NN * DD];             // [B,N,D]
__device__ float g_pos[(long)HH * NN * NN];           // [H,N,N]
__device__ float g_o[(long)BB * NN * DD];             // [B,N,D]

// ---------------- helpers ------------------------------------------------------
__device__ __forceinline__ void mma_bf16(float& d0, float& d1, float& d2, float& d3,
                                         unsigned a0, unsigned a1, unsigned a2, unsigned a3,
                                         unsigned b0, unsigned b1) {
    asm volatile(
        "mma.sync.aligned.m16n8k16.row.col.f32.bf16.bf16.f32 "
        "{%0,%1,%2,%3}, {%4,%5,%6,%7}, {%8,%9}, {%0,%1,%2,%3};\n"
        : "+f"(d0), "+f"(d1), "+f"(d2), "+f"(d3)
        : "r"(a0), "r"(a1), "r"(a2), "r"(a3), "r"(b0), "r"(b1));
}

__device__ __forceinline__ unsigned packbf2(__nv_bfloat16 x, __nv_bfloat16 y) {
    __nv_bfloat162 t;
    t.x = x; t.y = y;
    return *reinterpret_cast<unsigned*>(&t);
}

// split two fp32 into packed bf16x2 hi + lo residual words
__device__ __forceinline__ void split2(float x, float y, unsigned& hi, unsigned& lo) {
    __nv_bfloat16 hx = __float2bfloat16_rn(x), hy = __float2bfloat16_rn(y);
    hi = packbf2(hx, hy);
    lo = packbf2(__float2bfloat16_rn(x - __bfloat162float(hx)),
                 __float2bfloat16_rn(y - __bfloat162float(hy)));
}

// ---------------- split-bf16 GEMM: C = A[M,K] @ W[K,Nc] (+bias) ----------------
// 128x128 tile, K-chunk 32 (16 bf16x2 pairs). 8 warps = 2m x 4n (64x32 warp tile).
// A stored [m][kpair] stride 20; B (=W^T) stored [n][kpair] stride 20 via
// scalar-coalesced column gather. 3-term: Ah*Bh + Ah*Bl + Al*Bh.
#define GKP 20
#define G_A_WORDS (128 * GKP)                 // 2560 words
#define G_STG (4 * G_A_WORDS)                 // per stage: Ah, Al, Bh, Bl
#define GS_SMEM (2 * G_STG * 4)               // 81920 B

template <bool BIAS>
__global__ __launch_bounds__(256, 2) void gemm_bf16s(const float* __restrict__ A,
                                                     const float* __restrict__ W,
                                                     const float* __restrict__ bias,
                                                     float* __restrict__ C,
                                                     int M, int K, int Ncols) {
    extern __shared__ unsigned gsm[];
    const int tid = threadIdx.x;
    const int warp = tid >> 5, lane = tid & 31;
    const int wm = (warp & 1) * 64, wn = (warp >> 1) * 32;
    const int gp = lane >> 2, tg = lane & 3;
    const int bm = blockIdx.y * 128, bn = blockIdx.x * 128;

    float acc[4][4][4];
#pragma unroll
    for (int i = 0; i < 4; i++)
#pragma unroll
        for (int j = 0; j < 4; j++)
#pragma unroll
            for (int r = 0; r < 4; r++) acc[i][j][r] = 0.0f;

    float4 aS[4];
    float bS[16];
    const int kh = tid >> 7;       // B loader: k-half 0/1
    const int nn = tid & 127;      // B loader: n column
    const float* Abase = A + (long)bm * K;
    const float* Wcol = W + bn + nn;

#define G_LOAD(k0)                                                              \
    {                                                                           \
        _Pragma("unroll") for (int i = 0; i < 4; i++) {                         \
            int idx = tid + 256 * i;                                            \
            aS[i] = *(const float4*)(Abase + (long)(idx >> 3) * K + (k0) +      \
                                     (idx & 7) * 4);                            \
        }                                                                       \
        _Pragma("unroll") for (int j = 0; j < 16; j++)                          \
            bS[j] = Wcol[(long)((k0) + kh * 16 + j) * Ncols];                   \
    }

#define G_STORE(s)                                                              \
    {                                                                           \
        unsigned* Ah = gsm + (s) * G_STG;                                       \
        unsigned* Al = Ah + G_A_WORDS;                                          \
        unsigned* Bh = Al + G_A_WORDS;                                          \
        unsigned* Bl = Bh + G_A_WORDS;                                          \
        _Pragma("unroll") for (int i = 0; i < 4; i++) {                         \
            int idx = tid + 256 * i;                                            \
            int row = idx >> 3, p0 = (idx & 7) * 2;                             \
            unsigned h, l;                                                      \
            split2(aS[i].x, aS[i].y, h, l);                                     \
            Ah[row * GKP + p0] = h; Al[row * GKP + p0] = l;                     \
            split2(aS[i].z, aS[i].w, h, l);                                     \
            Ah[row * GKP + p0 + 1] = h; Al[row * GKP + p0 + 1] = l;             \
        }                                                                       \
        _Pragma("unroll") for (int i = 0; i < 8; i++) {                         \
            unsigned h, l;                                                      \
            split2(bS[2 * i], bS[2 * i + 1], h, l);                             \
            Bh[nn * GKP + kh * 8 + i] = h;                                      \
            Bl[nn * GKP + kh * 8 + i] = l;                                      \
        }                                                                       \
    }

#define G_COMPUTE(s)                                                            \
    {                                                                           \
        const unsigned* Ah = gsm + (s) * G_STG;                                 \
        const unsigned* Al = Ah + G_A_WORDS;                                    \
        const unsigned* Bh = Al + G_A_WORDS;                                    \
        const unsigned* Bl = Bh + G_A_WORDS;                                    \
        _Pragma("unroll") for (int st = 0; st < 2; st++) {                      \
            const int w0 = st * 8 + tg;                                         \
            unsigned ah[4][4], al[4][4];                                        \
            _Pragma("unroll") for (int ma = 0; ma < 4; ma++) {                  \
                const int r = (wm + ma * 16 + gp) * GKP;                        \
                ah[ma][0] = Ah[r + w0];                                         \
                ah[ma][1] = Ah[r + 8 * GKP + w0];                               \
                ah[ma][2] = Ah[r + w0 + 4];                                     \
                ah[ma][3] = Ah[r + 8 * GKP + w0 + 4];                           \
                al[ma][0] = Al[r + w0];                                         \
                al[ma][1] = Al[r + 8 * GKP + w0];                               \
                al[ma][2] = Al[r + w0 + 4];                                     \
                al[ma][3] = Al[r + 8 * GKP + w0 + 4];                           \
            }                                                                   \
            _Pragma("unroll") for (int nb = 0; nb < 4; nb++) {                  \
                const int nc = (wn + nb * 8 + gp) * GKP;                        \
                unsigned bh0 = Bh[nc + w0], bh1 = Bh[nc + w0 + 4];              \
                unsigned bl0 = Bl[nc + w0], bl1 = Bl[nc + w0 + 4];              \
                _Pragma("unroll") for (int ma = 0; ma < 4; ma++) {              \
                    mma_bf16(acc[ma][nb][0], acc[ma][nb][1], acc[ma][nb][2],    \
                             acc[ma][nb][3], ah[ma][0], ah[ma][1], ah[ma][2],   \
                             ah[ma][3], bh0, bh1);                              \
                    mma_bf16(acc[ma][nb][0], acc[ma][nb][1], acc[ma][nb][2],    \
                             acc[ma][nb][3], ah[ma][0], ah[ma][1], ah[ma][2],   \
                             ah[ma][3], bl0, bl1);                              \
                    mma_bf16(acc[ma][nb][0], acc[ma][nb][1], acc[ma][nb][2],    \
                             acc[ma][nb][3], al[ma][0], al[ma][1], al[ma][2],   \
                             al[ma][3], bh0, bh1);                              \
                }                                                               \
            }                                                                   \
        }                                                                       \
    }

    int s = 0;
    G_LOAD(0);
    G_STORE(0);
    __syncthreads();

    for (int k0 = 32; k0 < K; k0 += 32) {
        G_LOAD(k0);
        G_COMPUTE(s);
        G_STORE(s ^ 1);
        s ^= 1;
        __syncthreads();
    }
    G_COMPUTE(s);

#pragma unroll
    for (int ma = 0; ma < 4; ma++) {
        const long r0 = bm + wm + ma * 16 + gp;
        const long r1 = r0 + 8;
#pragma unroll
        for (int nb = 0; nb < 4; nb++) {
            const int col = bn + wn + nb * 8 + tg * 2;
            float2 v0 = make_float2(acc[ma][nb][0], acc[ma][nb][1]);
            float2 v1 = make_float2(acc[ma][nb][2], acc[ma][nb][3]);
            if (BIAS) {
                const float bb0 = __ldg(bias + col), bb1 = __ldg(bias + col + 1);
                v0.x += bb0; v0.y += bb1;
                v1.x += bb0; v1.y += bb1;
            }
            *(float2*)(C + r0 * Ncols + col) = v0;
            *(float2*)(C + r1 * Ncols + col) = v1;
        }
    }
#undef G_LOAD
#undef G_STORE
#undef G_COMPUTE
}

// ---------------- positional softmax: pos[h,n,:] = softmax(rel@W_pos+b) --------
__global__ __launch_bounds__(256) void pos_kernel(const float* __restrict__ rel,
                                                  const float* __restrict__ Wp,
                                                  const float* __restrict__ bp,
                                                  float* __restrict__ pos) {
    const int n = blockIdx.x, h = blockIdx.y, tid = threadIdx.x;
    __shared__ float red[8];
    __shared__ float bcv;
    const float w0 = Wp[h], w1 = Wp[HH + h], w2 = Wp[2 * HH + h], bb = bp[h];
    const float* r = rel + (long)n * NN * 3;

    float s0, s1, s2 = -1e30f;
    {
        const float* p = r + tid * 3;
        s0 = p[0] * w0 + p[1] * w1 + p[2] * w2 + bb;
        p = r + (tid + 256) * 3;
        s1 = p[0] * w0 + p[1] * w1 + p[2] * w2 + bb;
        if (tid < 64) {
            p = r + (tid + 512) * 3;
            s2 = p[0] * w0 + p[1] * w1 + p[2] * w2 + bb;
        }
    }
    float mx = fmaxf(fmaxf(s0, s1), s2);
#pragma unroll
    for (int o = 16; o; o >>= 1) mx = fmaxf(mx, __shfl_xor_sync(~0u, mx, o));
    if ((tid & 31) == 0) red[tid >> 5] = mx;
    __syncthreads();
    if (tid == 0) {
        float m = red[0];
        for (int i = 1; i < 8; i++) m = fmaxf(m, red[i]);
        bcv = m;
    }
    __syncthreads();
    mx = bcv;
    float e0 = expf(s0 - mx), e1 = expf(s1 - mx);
    float e2 = (tid < 64) ? expf(s2 - mx) : 0.0f;
    float sum = e0 + e1 + e2;
#pragma unroll
    for (int o = 16; o; o >>= 1) sum += __shfl_xor_sync(~0u, sum, o);
    __syncthreads();
    if ((tid & 31) == 0) red[tid >> 5] = sum;
    __syncthreads();
    if (tid == 0) {
        float s = 0.f;
        for (int i = 0; i < 8; i++) s += red[i];
        bcv = 1.0f / s;
    }
    __syncthreads();
    const float inv = bcv;
    float* out = pos + ((long)h * NN + n) * NN;
    out[tid] = e0 * inv;
    out[tid + 256] = e1 * inv;
    if (tid < 64) out[tid + 512] = e2 * inv;
}

// ---------------- fused one-pass attention, all-bf16 mma ------------------------
// Block = (b, h, 64 q-rows). S = split-bf16 q@k^T; exp (no max-sub);
// O_c += P@v and O_p += pos@v both as split-bf16 m16n8k16 (V transposed to
// [d][kpair] via scalar gather; P D-frag -> A-frag is an identity pack).
#define PB 36
#define FA_SMEM (8 * 64 * PB * 4)   // 73728 B

__global__ __launch_bounds__(256, 2) void fused_attn(
    const float* __restrict__ qk, const float* __restrict__ v,
    const float* __restrict__ pos, const float* __restrict__ gating,
    float* __restrict__ o) {
    extern __shared__ unsigned smem[];
    unsigned* qsb_h = smem;                 // [64][36] bf16x2 d-pairs
    unsigned* qsb_l = qsb_h + 64 * PB;
    unsigned* ksb_h = qsb_l + 64 * PB;      // [64 seq][36]
    unsigned* ksb_l = ksb_h + 64 * PB;
    unsigned* ps_h  = ksb_l + 64 * PB;      // [64 qrow][36 kpair]
    unsigned* ps_l  = ps_h + 64 * PB;
    unsigned* vt_h  = ps_l + 64 * PB;       // [64 d][36 kpair]  (V^T)
    unsigned* vt_l  = vt_h + 64 * PB;

    const int tid = threadIdx.x, warp = tid >> 5, lane = tid & 31;
    const int gp = lane >> 2, tg = lane & 3;
    const int wm = (warp & 3) * 16;         // warp's 16 q-rows
    const int wh = warp >> 2;               // k-half (S cols wh*32..+32)
    const int n0 = blockIdx.x * 64;
    const int b = blockIdx.y >> 4, h = blockIdx.y & 15;

    const float* qbase = qk + (long)b * NN * 2048 + h * 64;
    const float* kbase = qbase + 1024;
    const float* pbase = pos + ((long)h * NN + n0) * NN;

    // ---- load q tile (bf16 hi/lo split, packed pairs) ----
    {
        int idx = tid;
#pragma unroll
        for (int i = 0; i < 4; i++, idx += 256) {
            int r = idx >> 4, c4 = (idx & 15) * 4;
            float4 a = *(const float4*)(qbase + (long)(n0 + r) * 2048 + c4);
            unsigned hh, ll;
            split2(a.x, a.y, hh, ll);
            qsb_h[r * PB + (c4 >> 1)] = hh; qsb_l[r * PB + (c4 >> 1)] = ll;
            split2(a.z, a.w, hh, ll);
            qsb_h[r * PB + (c4 >> 1) + 1] = hh; qsb_l[r * PB + (c4 >> 1) + 1] = ll;
        }
    }

    float Oc[8][4], Op[8][4];
#pragma unroll
    for (int i = 0; i < 8; i++)
#pragma unroll
        for (int j = 0; j < 4; j++) { Oc[i][j] = 0.0f; Op[i][j] = 0.0f; }
    float l0 = 0.0f, l1 = 0.0f;
    const float scale = 0.125f;

    const int vd = tid & 63, vkg = tid >> 6;   // v-transpose loader mapping

    for (int m0 = 0; m0 < NN; m0 += 64) {
        __syncthreads();
        // ---- k tile (bf16 hi/lo pairs) + pos tile + v^T tile ----
        {
            int idx = tid;
#pragma unroll
            for (int i = 0; i < 4; i++, idx += 256) {
                int r = idx >> 4, c4 = (idx & 15) * 4;
                float4 a = *(const float4*)(kbase + (long)(m0 + r) * 2048 + c4);
                unsigned hh, ll;
                split2(a.x, a.y, hh, ll);
                ksb_h[r * PB + (c4 >> 1)] = hh; ksb_l[r * PB + (c4 >> 1)] = ll;
                split2(a.z, a.w, hh, ll);
                ksb_h[r * PB + (c4 >> 1) + 1] = hh; ksb_l[r * PB + (c4 >> 1) + 1] = ll;
                float4 pp = *(const float4*)(pbase + (long)r * NN + m0 + c4);
                split2(pp.x, pp.y, hh, ll);
                ps_h[r * PB + (c4 >> 1)] = hh; ps_l[r * PB + (c4 >> 1)] = ll;
                split2(pp.z, pp.w, hh, ll);
                ps_h[r * PB + (c4 >> 1) + 1] = hh; ps_l[r * PB + (c4 >> 1) + 1] = ll;
            }
            // v^T: thread gathers 16 k-values for one d column
            const float* vp = v + ((long)b * NN + m0 + vkg * 16) * DD + h * 64 + vd;
            float vv[16];
#pragma unroll
            for (int j = 0; j < 16; j++) vv[j] = vp[(long)j * DD];
#pragma unroll
            for (int i = 0; i < 8; i++) {
                unsigned hh, ll;
                split2(vv[2 * i], vv[2 * i + 1], hh, ll);
                vt_h[vd * PB + vkg * 8 + i] = hh;
                vt_l[vd * PB + vkg * 8 + i] = ll;
            }
        }
        __syncthreads();

        // ---- S = q @ k^T over warp's 16x32 slice (split-bf16) ----
        float p[4][4];
#pragma unroll
        for (int i = 0; i < 4; i++)
#pragma unroll
            for (int j = 0; j < 4; j++) p[i][j] = 0.0f;

        const int rowA = (wm + gp) * PB;
#pragma unroll
        for (int kc = 0; kc < 4; kc++) {
            const int d2 = kc * 8 + tg;
            unsigned ah0 = qsb_h[rowA + d2];
            unsigned ah1 = qsb_h[rowA + 8 * PB + d2];
            unsigned ah2 = qsb_h[rowA + d2 + 4];
            unsigned ah3 = qsb_h[rowA + 8 * PB + d2 + 4];
            unsigned al0 = qsb_l[rowA + d2];
            unsigned al1 = qsb_l[rowA + 8 * PB + d2];
            unsigned al2 = qsb_l[rowA + d2 + 4];
            unsigned al3 = qsb_l[rowA + 8 * PB + d2 + 4];
#pragma unroll
            for (int na = 0; na < 4; na++) {
                const int rowB = (wh * 32 + na * 8 + gp) * PB;
                unsigned bh0 = ksb_h[rowB + d2];
                unsigned bh1 = ksb_h[rowB + d2 + 4];
                unsigned bl0 = ksb_l[rowB + d2];
                unsigned bl1 = ksb_l[rowB + d2 + 4];
                mma_bf16(p[na][0], p[na][1], p[na][2], p[na][3],
                         ah0, ah1, ah2, ah3, bh0, bh1);
                mma_bf16(p[na][0], p[na][1], p[na][2], p[na][3],
                         ah0, ah1, ah2, ah3, bl0, bl1);
                mma_bf16(p[na][0], p[na][1], p[na][2], p[na][3],
                         al0, al1, al2, al3, bh0, bh1);
            }
        }

        // ---- exp (no max-sub), row sums, pack P into bf16 A-frags (identity) ----
        unsigned Ph[2][4], Pl[2][4];
#pragma unroll
        for (int na = 0; na < 4; na++) {
            p[na][0] = __expf(p[na][0] * scale);
            p[na][1] = __expf(p[na][1] * scale);
            p[na][2] = __expf(p[na][2] * scale);
            p[na][3] = __expf(p[na][3] * scale);
            l0 += p[na][0] + p[na][1];
            l1 += p[na][2] + p[na][3];
        }
#pragma unroll
        for (int s = 0; s < 2; s++) {
            split2(p[2 * s][0],     p[2 * s][1],     Ph[s][0], Pl[s][0]);
            split2(p[2 * s][2],     p[2 * s][3],     Ph[s][1], Pl[s][1]);
            split2(p[2 * s + 1][0], p[2 * s + 1][1], Ph[s][2], Pl[s][2]);
            split2(p[2 * s + 1][2], p[2 * s + 1][3], Ph[s][3], Pl[s][3]);
        }

        // ---- O_c += P@v, O_p += pos@v (split-bf16) ----
#pragma unroll
        for (int s = 0; s < 2; s++) {
            const int wb = wh * 16 + s * 8 + tg;
            const int rA = (wm + gp) * PB + wb;
            unsigned ph0 = ps_h[rA],           ph1 = ps_h[rA + 8 * PB];
            unsigned ph2 = ps_h[rA + 4],       ph3 = ps_h[rA + 8 * PB + 4];
            unsigned pl0 = ps_l[rA],           pl1 = ps_l[rA + 8 * PB];
            unsigned pl2 = ps_l[rA + 4],       pl3 = ps_l[rA + 8 * PB + 4];
#pragma unroll
            for (int nv = 0; nv < 8; nv++) {
                const int rB = (nv * 8 + gp) * PB + wb;
                unsigned bh0 = vt_h[rB], bh1 = vt_h[rB + 4];
                unsigned bl0 = vt_l[rB], bl1 = vt_l[rB + 4];
                mma_bf16(Oc[nv][0], Oc[nv][1], Oc[nv][2], Oc[nv][3],
                         Ph[s][0], Ph[s][1], Ph[s][2], Ph[s][3], bh0, bh1);
                mma_bf16(Oc[nv][0], Oc[nv][1], Oc[nv][2], Oc[nv][3],
                         Ph[s][0], Ph[s][1], Ph[s][2], Ph[s][3], bl0, bl1);
                mma_bf16(Oc[nv][0], Oc[nv][1], Oc[nv][2], Oc[nv][3],
                         Pl[s][0], Pl[s][1], Pl[s][2], Pl[s][3], bh0, bh1);
                mma_bf16(Op[nv][0], Op[nv][1], Op[nv][2], Op[nv][3],
                         ph0, ph1, ph2, ph3, bh0, bh1);
                mma_bf16(Op[nv][0], Op[nv][1], Op[nv][2], Op[nv][3],
                         ph0, ph1, ph2, ph3, bl0, bl1);
                mma_bf16(Op[nv][0], Op[nv][1], Op[nv][2], Op[nv][3],
                         pl0, pl1, pl2, pl3, bh0, bh1);
            }
        }
    }

    // ---- reduce row-sums within tg group ----
    l0 += __shfl_xor_sync(~0u, l0, 1); l0 += __shfl_xor_sync(~0u, l0, 2);
    l1 += __shfl_xor_sync(~0u, l1, 1); l1 += __shfl_xor_sync(~0u, l1, 2);

    // ---- combine warp-half partials via smem scratch ----
    float* sOc = (float*)smem;          // [64][65]
    float* sOp = sOc + 64 * 65;
    float* slb = sOp + 64 * 65;
    __syncthreads();
    if (wh == 1) {
#pragma unroll
        for (int nv = 0; nv < 8; nv++) {
            const int base = (wm + gp) * 65 + nv * 8 + 2 * tg;
            sOc[base]              = Oc[nv][0];
            sOc[base + 1]          = Oc[nv][1];
            sOc[base + 8 * 65]     = Oc[nv][2];
            sOc[base + 8 * 65 + 1] = Oc[nv][3];
            sOp[base]              = Op[nv][0];
            sOp[base + 1]          = Op[nv][1];
            sOp[base + 8 * 65]     = Op[nv][2];
            sOp[base + 8 * 65 + 1] = Op[nv][3];
        }
        slb[wm + gp] = l0;
        slb[wm + gp + 8] = l1;
    }
    __syncthreads();
    if (wh == 0) {
        const float g = 1.0f / (1.0f + __expf(-gating[h]));
        const float og = 1.0f - g;
        const float lt0 = l0 + slb[wm + gp];
        const float lt1 = l1 + slb[wm + gp + 8];
        const float c0 = og / lt0, c1 = og / lt1;
        const long row = n0 + wm + gp;
        float* dst0 = o + ((long)b * NN + row) * DD + h * 64;
#pragma unroll
        for (int nv = 0; nv < 8; nv++) {
            const int base = (wm + gp) * 65 + nv * 8 + 2 * tg;
            float oc0 = Oc[nv][0] + sOc[base];
            float oc1 = Oc[nv][1] + sOc[base + 1];
            float oc2 = Oc[nv][2] + sOc[base + 8 * 65];
            float oc3 = Oc[nv][3] + sOc[base + 8 * 65 + 1];
            float op0 = Op[nv][0] + sOp[base];
            float op1 = Op[nv][1] + sOp[base + 1];
            float op2 = Op[nv][2] + sOp[base + 8 * 65];
            float op3 = Op[nv][3] + sOp[base + 8 * 65 + 1];
            float* dst = dst0 + nv * 8 + 2 * tg;
            *(float2*)dst = make_float2(c0 * oc0 + g * op0, c0 * oc1 + g * op1);
            *(float2*)(dst + 8L * DD) = make_float2(c1 * oc2 + g * op2, c1 * oc3 + g * op3);
        }
    }
}

// ---------------- launch ----------------
extern "C" void kernel_launch(void* const* d_in, const int* in_sizes, int n_in,
                              void* d_out, int out_size) {
    const float* x      = (const float*)d_in[0];
    const float* W_qk   = (const float*)d_in[1];
    const float* W_v    = (const float*)d_in[2];
    const float* W_proj = (const float*)d_in[3];
    const float* b_proj = (const float*)d_in[4];
    const float* W_pos  = (const float*)d_in[5];
    const float* b_pos  = (const float*)d_in[6];
    const float* gating = (const float*)d_in[7];
    const float* rel    = (const float*)d_in[8];
    float* out = (float*)d_out;

    float* qk;   cudaGetSymbolAddress((void**)&qk,   g_qk);
    float* vbuf; cudaGetSymbolAddress((void**)&vbuf, g_v);
    float* pos;  cudaGetSymbolAddress((void**)&pos,  g_pos);
    float* obuf; cudaGetSymbolAddress((void**)&obuf, g_o);

    cudaFuncSetAttribute(gemm_bf16s<false>, cudaFuncAttributeMaxDynamicSharedMemorySize, GS_SMEM);
    cudaFuncSetAttribute(gemm_bf16s<true>,  cudaFuncAttributeMaxDynamicSharedMemorySize, GS_SMEM);
    cudaFuncSetAttribute(fused_attn, cudaFuncAttributeMaxDynamicSharedMemorySize, FA_SMEM);

    const int M = BB * NN;  // 9216

    // 1) qk = x @ W_qk
    gemm_bf16s<false><<<dim3(2 * DD / 128, M / 128), 256, GS_SMEM>>>(x, W_qk, nullptr, qk, M, DD, 2 * DD);
    // 2) v = x @ W_v
    gemm_bf16s<false><<<dim3(DD / 128, M / 128), 256, GS_SMEM>>>(x, W_v, nullptr, vbuf, M, DD, DD);
    // 3) positional softmax
    pos_kernel<<<dim3(NN, HH), 256>>>(rel, W_pos, b_pos, pos);
    // 4) fused one-pass attention (all-bf16 mma)
    fused_attn<<<dim3(NN / 64, BB * HH), 256, FA_SMEM>>>(qk, vbuf, pos, gating, obuf);
    // 5) out = o @ W_proj + b_proj
    gemm_bf16s<true><<<dim3(DD / 128, M / 128), 256, GS_SMEM>>>(obuf, W_proj, b_proj, out, M, DD, DD);
}

// round 9
// speedup vs baseline: 1.7441x; 1.7441x over previous
#include <cuda_runtime.h>
#include <cuda_fp16.h>
#include <cstdint>

#define BB 16
#define NN 576
#define DD 1024
#define HH 16
#define HD 64

// ---------------- scratch (static device globals; no allocation) ----------------
__device__ float g_qk[(long)BB * NN * 2 * DD];        // [B,N,2D]
__device__ float g_v[(long)BB * NN * DD];             // [B,N,D]
__device__ float g_pos[(long)HH * NN * NN];           // [H,N,N]
__device__ float g_o[(long)BB * NN * DD];             // [B,N,D]

// ---------------- helpers ------------------------------------------------------
__device__ __forceinline__ void mma_fp16(float& d0, float& d1, float& d2, float& d3,
                                         unsigned a0, unsigned a1, unsigned a2, unsigned a3,
                                         unsigned b0, unsigned b1) {
    asm volatile(
        "mma.sync.aligned.m16n8k16.row.col.f32.f16.f16.f32 "
        "{%0,%1,%2,%3}, {%4,%5,%6,%7}, {%8,%9}, {%0,%1,%2,%3};\n"
        : "+f"(d0), "+f"(d1), "+f"(d2), "+f"(d3)
        : "r"(a0), "r"(a1), "r"(a2), "r"(a3), "r"(b0), "r"(b1));
}

__device__ __forceinline__ unsigned packh2(__half x, __half y) {
    __half2 t;
    t.x = x; t.y = y;
    return *reinterpret_cast<unsigned*>(&t);
}

// plain fp16 pack of two fp32
__device__ __forceinline__ unsigned pack2f(float x, float y) {
    return packh2(__float2half_rn(x), __float2half_rn(y));
}

// split two fp32 into fp16x2 hi + lo residual words
__device__ __forceinline__ void split2h(float x, float y, unsigned& hi, unsigned& lo) {
    __half hx = __float2half_rn(x), hy = __float2half_rn(y);
    hi = packh2(hx, hy);
    lo = packh2(__float2half_rn(x - __half2float(hx)),
                __float2half_rn(y - __half2float(hy)));
}

// ---------------- plain-fp16 GEMM: C = A[M,K] @ W[K,Nc] (+bias) ----------------
// 128x128 tile, K-chunk 32 (16 fp16x2 pairs). 8 warps = 2m x 4n (64x32 warp tile).
// A stored [m][kpair] stride 20; B (=W^T) stored [n][kpair] stride 20 via
// scalar-coalesced column gather. Double-buffered.
#define GKP 20
#define G_A_WORDS (128 * GKP)                 // 2560 words
#define G_STG (2 * G_A_WORDS)                 // per stage: A, B
#define GS_SMEM (2 * G_STG * 4)               // 40960 B

template <bool BIAS>
__global__ __launch_bounds__(256, 2) void gemm_fp16(const float* __restrict__ A,
                                                    const float* __restrict__ W,
                                                    const float* __restrict__ bias,
                                                    float* __restrict__ C,
                                                    int M, int K, int Ncols) {
    extern __shared__ unsigned gsm[];
    const int tid = threadIdx.x;
    const int warp = tid >> 5, lane = tid & 31;
    const int wm = (warp & 1) * 64, wn = (warp >> 1) * 32;
    const int gp = lane >> 2, tg = lane & 3;
    const int bm = blockIdx.y * 128, bn = blockIdx.x * 128;

    float acc[4][4][4];
#pragma unroll
    for (int i = 0; i < 4; i++)
#pragma unroll
        for (int j = 0; j < 4; j++)
#pragma unroll
            for (int r = 0; r < 4; r++) acc[i][j][r] = 0.0f;

    float4 aS[4];
    float bS[16];
    const int kh = tid >> 7;       // B loader: k-half 0/1
    const int nn = tid & 127;      // B loader: n column
    const float* Abase = A + (long)bm * K;
    const float* Wcol = W + bn + nn;

#define G_LOAD(k0)                                                              \
    {                                                                           \
        _Pragma("unroll") for (int i = 0; i < 4; i++) {                         \
            int idx = tid + 256 * i;                                            \
            aS[i] = *(const float4*)(Abase + (long)(idx >> 3) * K + (k0) +      \
                                     (idx & 7) * 4);                            \
        }                                                                       \
        _Pragma("unroll") for (int j = 0; j < 16; j++)                          \
            bS[j] = Wcol[(long)((k0) + kh * 16 + j) * Ncols];                   \
    }

#define G_STORE(s)                                                              \
    {                                                                           \
        unsigned* Ad = gsm + (s) * G_STG;                                       \
        unsigned* Bd = Ad + G_A_WORDS;                                          \
        _Pragma("unroll") for (int i = 0; i < 4; i++) {                         \
            int idx = tid + 256 * i;                                            \
            int row = idx >> 3, p0 = (idx & 7) * 2;                             \
            Ad[row * GKP + p0]     = pack2f(aS[i].x, aS[i].y);                  \
            Ad[row * GKP + p0 + 1] = pack2f(aS[i].z, aS[i].w);                  \
        }                                                                       \
        _Pragma("unroll") for (int i = 0; i < 8; i++)                           \
            Bd[nn * GKP + kh * 8 + i] = pack2f(bS[2 * i], bS[2 * i + 1]);       \
    }

#define G_COMPUTE(s)                                                            \
    {                                                                           \
        const unsigned* Ar = gsm + (s) * G_STG;                                 \
        const unsigned* Br = Ar + G_A_WORDS;                                    \
        _Pragma("unroll") for (int st = 0; st < 2; st++) {                      \
            const int w0 = st * 8 + tg;                                         \
            unsigned af[4][4];                                                  \
            _Pragma("unroll") for (int ma = 0; ma < 4; ma++) {                  \
                const int r = (wm + ma * 16 + gp) * GKP;                        \
                af[ma][0] = Ar[r + w0];                                         \
                af[ma][1] = Ar[r + 8 * GKP + w0];                               \
                af[ma][2] = Ar[r + w0 + 4];                                     \
                af[ma][3] = Ar[r + 8 * GKP + w0 + 4];                           \
            }                                                                   \
            _Pragma("unroll") for (int nb = 0; nb < 4; nb++) {                  \
                const int nc = (wn + nb * 8 + gp) * GKP;                        \
                unsigned b0 = Br[nc + w0], b1 = Br[nc + w0 + 4];                \
                _Pragma("unroll") for (int ma = 0; ma < 4; ma++)                \
                    mma_fp16(acc[ma][nb][0], acc[ma][nb][1], acc[ma][nb][2],    \
                             acc[ma][nb][3], af[ma][0], af[ma][1], af[ma][2],   \
                             af[ma][3], b0, b1);                                \
            }                                                                   \
        }                                                                       \
    }

    int s = 0;
    G_LOAD(0);
    G_STORE(0);
    __syncthreads();

    for (int k0 = 32; k0 < K; k0 += 32) {
        G_LOAD(k0);
        G_COMPUTE(s);
        G_STORE(s ^ 1);
        s ^= 1;
        __syncthreads();
    }
    G_COMPUTE(s);

#pragma unroll
    for (int ma = 0; ma < 4; ma++) {
        const long r0 = bm + wm + ma * 16 + gp;
        const long r1 = r0 + 8;
#pragma unroll
        for (int nb = 0; nb < 4; nb++) {
            const int col = bn + wn + nb * 8 + tg * 2;
            float2 v0 = make_float2(acc[ma][nb][0], acc[ma][nb][1]);
            float2 v1 = make_float2(acc[ma][nb][2], acc[ma][nb][3]);
            if (BIAS) {
                const float bb0 = __ldg(bias + col), bb1 = __ldg(bias + col + 1);
                v0.x += bb0; v0.y += bb1;
                v1.x += bb0; v1.y += bb1;
            }
            *(float2*)(C + r0 * Ncols + col) = v0;
            *(float2*)(C + r1 * Ncols + col) = v1;
        }
    }
#undef G_LOAD
#undef G_STORE
#undef G_COMPUTE
}

// ---------------- positional softmax: pos[h,n,:] = softmax(rel@W_pos+b) --------
__global__ __launch_bounds__(256) void pos_kernel(const float* __restrict__ rel,
                                                  const float* __restrict__ Wp,
                                                  const float* __restrict__ bp,
                                                  float* __restrict__ pos) {
    const int n = blockIdx.x, h = blockIdx.y, tid = threadIdx.x;
    __shared__ float red[8];
    __shared__ float bcv;
    const float w0 = Wp[h], w1 = Wp[HH + h], w2 = Wp[2 * HH + h], bb = bp[h];
    const float* r = rel + (long)n * NN * 3;

    float s0, s1, s2 = -1e30f;
    {
        const float* p = r + tid * 3;
        s0 = p[0] * w0 + p[1] * w1 + p[2] * w2 + bb;
        p = r + (tid + 256) * 3;
        s1 = p[0] * w0 + p[1] * w1 + p[2] * w2 + bb;
        if (tid < 64) {
            p = r + (tid + 512) * 3;
            s2 = p[0] * w0 + p[1] * w1 + p[2] * w2 + bb;
        }
    }
    float mx = fmaxf(fmaxf(s0, s1), s2);
#pragma unroll
    for (int o = 16; o; o >>= 1) mx = fmaxf(mx, __shfl_xor_sync(~0u, mx, o));
    if ((tid & 31) == 0) red[tid >> 5] = mx;
    __syncthreads();
    if (tid == 0) {
        float m = red[0];
        for (int i = 1; i < 8; i++) m = fmaxf(m, red[i]);
        bcv = m;
    }
    __syncthreads();
    mx = bcv;
    float e0 = expf(s0 - mx), e1 = expf(s1 - mx);
    float e2 = (tid < 64) ? expf(s2 - mx) : 0.0f;
    float sum = e0 + e1 + e2;
#pragma unroll
    for (int o = 16; o; o >>= 1) sum += __shfl_xor_sync(~0u, sum, o);
    __syncthreads();
    if ((tid & 31) == 0) red[tid >> 5] = sum;
    __syncthreads();
    if (tid == 0) {
        float s = 0.f;
        for (int i = 0; i < 8; i++) s += red[i];
        bcv = 1.0f / s;
    }
    __syncthreads();
    const float inv = bcv;
    float* out = pos + ((long)h * NN + n) * NN;
    out[tid] = e0 * inv;
    out[tid + 256] = e1 * inv;
    if (tid < 64) out[tid + 512] = e2 * inv;
}

// ---------------- fused one-pass attention -------------------------------------
// Block = (b, h, 64 q-rows). S = split-fp16 3-term q@k^T (48 mma/tile).
// exp (no max-sub; logits bounded). PV phase in PLAIN fp16 k16 (32 mma/tile):
// P D-frag -> A-frag is an identity pack; pos and v^T plain fp16 pairs.
// Final: out = (1-g)*O_c/l + g*O_p.
#define PB 36
#define FA_SMEM (6 * 64 * PB * 4)   // 55296 B

__global__ __launch_bounds__(256, 2) void fused_attn(
    const float* __restrict__ qk, const float* __restrict__ v,
    const float* __restrict__ pos, const float* __restrict__ gating,
    float* __restrict__ o) {
    extern __shared__ unsigned smem[];
    unsigned* qs_h = smem;                 // [64][36] fp16x2 d-pairs
    unsigned* qs_l = qs_h + 64 * PB;
    unsigned* ks_h = qs_l + 64 * PB;       // [64 seq][36]
    unsigned* ks_l = ks_h + 64 * PB;
    unsigned* ps   = ks_l + 64 * PB;       // [64 qrow][36] fp16x2 seq-pairs
    unsigned* vt   = ps + 64 * PB;         // [64 d][36]  (V^T, fp16x2 seq-pairs)

    const int tid = threadIdx.x, warp = tid >> 5, lane = tid & 31;
    const int gp = lane >> 2, tg = lane & 3;
    const int wm = (warp & 3) * 16;        // warp's 16 q-rows
    const int wh = warp >> 2;              // k-half (S cols wh*32..+32)
    const int n0 = blockIdx.x * 64;
    const int b = blockIdx.y >> 4, h = blockIdx.y & 15;

    const float* qbase = qk + (long)b * NN * 2048 + h * 64;
    const float* kbase = qbase + 1024;
    const float* pbase = pos + ((long)h * NN + n0) * NN;

    // ---- load q tile (fp16 hi/lo split, packed pairs) ----
    {
        int idx = tid;
#pragma unroll
        for (int i = 0; i < 4; i++, idx += 256) {
            int r = idx >> 4, c4 = (idx & 15) * 4;
            float4 a = *(const float4*)(qbase + (long)(n0 + r) * 2048 + c4);
            unsigned hh, ll;
            split2h(a.x, a.y, hh, ll);
            qs_h[r * PB + (c4 >> 1)] = hh; qs_l[r * PB + (c4 >> 1)] = ll;
            split2h(a.z, a.w, hh, ll);
            qs_h[r * PB + (c4 >> 1) + 1] = hh; qs_l[r * PB + (c4 >> 1) + 1] = ll;
        }
    }

    float Oc[8][4], Op[8][4];
#pragma unroll
    for (int i = 0; i < 8; i++)
#pragma unroll
        for (int j = 0; j < 4; j++) { Oc[i][j] = 0.0f; Op[i][j] = 0.0f; }
    float l0 = 0.0f, l1 = 0.0f;
    const float scale = 0.125f;

    const int vd = tid & 63, vkg = tid >> 6;   // v-transpose loader mapping

    for (int m0 = 0; m0 < NN; m0 += 64) {
        __syncthreads();
        // ---- k tile (fp16 hi/lo pairs) + pos tile + v^T tile ----
        {
            int idx = tid;
#pragma unroll
            for (int i = 0; i < 4; i++, idx += 256) {
                int r = idx >> 4, c4 = (idx & 15) * 4;
                float4 a = *(const float4*)(kbase + (long)(m0 + r) * 2048 + c4);
                unsigned hh, ll;
                split2h(a.x, a.y, hh, ll);
                ks_h[r * PB + (c4 >> 1)] = hh; ks_l[r * PB + (c4 >> 1)] = ll;
                split2h(a.z, a.w, hh, ll);
                ks_h[r * PB + (c4 >> 1) + 1] = hh; ks_l[r * PB + (c4 >> 1) + 1] = ll;
                float4 pp = *(const float4*)(pbase + (long)r * NN + m0 + c4);
                ps[r * PB + (c4 >> 1)]     = pack2f(pp.x, pp.y);
                ps[r * PB + (c4 >> 1) + 1] = pack2f(pp.z, pp.w);
            }
            // v^T: thread gathers 16 seq-values for one d column
            const float* vp = v + ((long)b * NN + m0 + vkg * 16) * DD + h * 64 + vd;
            float vv[16];
#pragma unroll
            for (int j = 0; j < 16; j++) vv[j] = vp[(long)j * DD];
#pragma unroll
            for (int i = 0; i < 8; i++)
                vt[vd * PB + vkg * 8 + i] = pack2f(vv[2 * i], vv[2 * i + 1]);
        }
        __syncthreads();

        // ---- S = q @ k^T over warp's 16x32 slice (split-fp16, 3 terms) ----
        float p[4][4];
#pragma unroll
        for (int i = 0; i < 4; i++)
#pragma unroll
            for (int j = 0; j < 4; j++) p[i][j] = 0.0f;

        const int rowA = (wm + gp) * PB;
#pragma unroll
        for (int kc = 0; kc < 4; kc++) {
            const int d2 = kc * 8 + tg;
            unsigned ah0 = qs_h[rowA + d2];
            unsigned ah1 = qs_h[rowA + 8 * PB + d2];
            unsigned ah2 = qs_h[rowA + d2 + 4];
            unsigned ah3 = qs_h[rowA + 8 * PB + d2 + 4];
            unsigned al0 = qs_l[rowA + d2];
            unsigned al1 = qs_l[rowA + 8 * PB + d2];
            unsigned al2 = qs_l[rowA + d2 + 4];
            unsigned al3 = qs_l[rowA + 8 * PB + d2 + 4];
#pragma unroll
            for (int na = 0; na < 4; na++) {
                const int rowB = (wh * 32 + na * 8 + gp) * PB;
                unsigned bh0 = ks_h[rowB + d2];
                unsigned bh1 = ks_h[rowB + d2 + 4];
                unsigned bl0 = ks_l[rowB + d2];
                unsigned bl1 = ks_l[rowB + d2 + 4];
                mma_fp16(p[na][0], p[na][1], p[na][2], p[na][3],
                         ah0, ah1, ah2, ah3, bh0, bh1);
                mma_fp16(p[na][0], p[na][1], p[na][2], p[na][3],
                         ah0, ah1, ah2, ah3, bl0, bl1);
                mma_fp16(p[na][0], p[na][1], p[na][2], p[na][3],
                         al0, al1, al2, al3, bh0, bh1);
            }
        }

        // ---- exp (no max-sub), row sums, pack P into fp16 A-frags (identity) ----
#pragma unroll
        for (int na = 0; na < 4; na++) {
            p[na][0] = __expf(p[na][0] * scale);
            p[na][1] = __expf(p[na][1] * scale);
            p[na][2] = __expf(p[na][2] * scale);
            p[na][3] = __expf(p[na][3] * scale);
            l0 += p[na][0] + p[na][1];
            l1 += p[na][2] + p[na][3];
        }

        // ---- O_c += P@v, O_p += pos@v (plain fp16 k16) ----
#pragma unroll
        for (int s = 0; s < 2; s++) {
            unsigned Pa0 = pack2f(p[2 * s][0],     p[2 * s][1]);
            unsigned Pa1 = pack2f(p[2 * s][2],     p[2 * s][3]);
            unsigned Pa2 = pack2f(p[2 * s + 1][0], p[2 * s + 1][1]);
            unsigned Pa3 = pack2f(p[2 * s + 1][2], p[2 * s + 1][3]);

            const int wb = wh * 16 + s * 8 + tg;
            const int rA = (wm + gp) * PB + wb;
            unsigned pa0 = ps[rA],     pa1 = ps[rA + 8 * PB];
            unsigned pa2 = ps[rA + 4], pa3 = ps[rA + 8 * PB + 4];
#pragma unroll
            for (int nv = 0; nv < 8; nv++) {
                const int rB = (nv * 8 + gp) * PB + wb;
                unsigned b0 = vt[rB], b1 = vt[rB + 4];
                mma_fp16(Oc[nv][0], Oc[nv][1], Oc[nv][2], Oc[nv][3],
                         Pa0, Pa1, Pa2, Pa3, b0, b1);
                mma_fp16(Op[nv][0], Op[nv][1], Op[nv][2], Op[nv][3],
                         pa0, pa1, pa2, pa3, b0, b1);
            }
        }
    }

    // ---- reduce row-sums within tg group ----
    l0 += __shfl_xor_sync(~0u, l0, 1); l0 += __shfl_xor_sync(~0u, l0, 2);
    l1 += __shfl_xor_sync(~0u, l1, 1); l1 += __shfl_xor_sync(~0u, l1, 2);

    // ---- combine warp-half partials via smem scratch ----
    float* sOc = (float*)smem;          // [64][65]
    float* sOp = sOc + 64 * 65;
    float* slb = sOp + 64 * 65;
    __syncthreads();
    if (wh == 1) {
#pragma unroll
        for (int nv = 0; nv < 8; nv++) {
            const int base = (wm + gp) * 65 + nv * 8 + 2 * tg;
            sOc[base]              = Oc[nv][0];
            sOc[base + 1]          = Oc[nv][1];
            sOc[base + 8 * 65]     = Oc[nv][2];
            sOc[base + 8 * 65 + 1] = Oc[nv][3];
            sOp[base]              = Op[nv][0];
            sOp[base + 1]          = Op[nv][1];
            sOp[base + 8 * 65]     = Op[nv][2];
            sOp[base + 8 * 65 + 1] = Op[nv][3];
        }
        slb[wm + gp] = l0;
        slb[wm + gp + 8] = l1;
    }
    __syncthreads();
    if (wh == 0) {
        const float g = 1.0f / (1.0f + __expf(-gating[h]));
        const float og = 1.0f - g;
        const float lt0 = l0 + slb[wm + gp];
        const float lt1 = l1 + slb[wm + gp + 8];
        const float c0 = og / lt0, c1 = og / lt1;
        const long row = n0 + wm + gp;
        float* dst0 = o + ((long)b * NN + row) * DD + h * 64;
#pragma unroll
        for (int nv = 0; nv < 8; nv++) {
            const int base = (wm + gp) * 65 + nv * 8 + 2 * tg;
            float oc0 = Oc[nv][0] + sOc[base];
            float oc1 = Oc[nv][1] + sOc[base + 1];
            float oc2 = Oc[nv][2] + sOc[base + 8 * 65];
            float oc3 = Oc[nv][3] + sOc[base + 8 * 65 + 1];
            float op0 = Op[nv][0] + sOp[base];
            float op1 = Op[nv][1] + sOp[base + 1];
            float op2 = Op[nv][2] + sOp[base + 8 * 65];
            float op3 = Op[nv][3] + sOp[base + 8 * 65 + 1];
            float* dst = dst0 + nv * 8 + 2 * tg;
            *(float2*)dst = make_float2(c0 * oc0 + g * op0, c0 * oc1 + g * op1);
            *(float2*)(dst + 8L * DD) = make_float2(c1 * oc2 + g * op2, c1 * oc3 + g * op3);
        }
    }
}

// ---------------- launch ----------------
extern "C" void kernel_launch(void* const* d_in, const int* in_sizes, int n_in,
                              void* d_out, int out_size) {
    const float* x      = (const float*)d_in[0];
    const float* W_qk   = (const float*)d_in[1];
    const float* W_v    = (const float*)d_in[2];
    const float* W_proj = (const float*)d_in[3];
    const float* b_proj = (const float*)d_in[4];
    const float* W_pos  = (const float*)d_in[5];
    const float* b_pos  = (const float*)d_in[6];
    const float* gating = (const float*)d_in[7];
    const float* rel    = (const float*)d_in[8];
    float* out = (float*)d_out;

    float* qk;   cudaGetSymbolAddress((void**)&qk,   g_qk);
    float* vbuf; cudaGetSymbolAddress((void**)&vbuf, g_v);
    float* pos;  cudaGetSymbolAddress((void**)&pos,  g_pos);
    float* obuf; cudaGetSymbolAddress((void**)&obuf, g_o);

    cudaFuncSetAttribute(gemm_fp16<false>, cudaFuncAttributeMaxDynamicSharedMemorySize, GS_SMEM);
    cudaFuncSetAttribute(gemm_fp16<true>,  cudaFuncAttributeMaxDynamicSharedMemorySize, GS_SMEM);
    cudaFuncSetAttribute(fused_attn, cudaFuncAttributeMaxDynamicSharedMemorySize, FA_SMEM);

    const int M = BB * NN;  // 9216

    // 1) qk = x @ W_qk
    gemm_fp16<false><<<dim3(2 * DD / 128, M / 128), 256, GS_SMEM>>>(x, W_qk, nullptr, qk, M, DD, 2 * DD);
    // 2) v = x @ W_v
    gemm_fp16<false><<<dim3(DD / 128, M / 128), 256, GS_SMEM>>>(x, W_v, nullptr, vbuf, M, DD, DD);
    // 3) positional softmax
    pos_kernel<<<dim3(NN, HH), 256>>>(rel, W_pos, b_pos, pos);
    // 4) fused one-pass attention
    fused_attn<<<dim3(NN / 64, BB * HH), 256, FA_SMEM>>>(qk, vbuf, pos, gating, obuf);
    // 5) out = o @ W_proj + b_proj
    gemm_fp16<true><<<dim3(DD / 128, M / 128), 256, GS_SMEM>>>(obuf, W_proj, b_proj, out, M, DD, DD);
}

// round 10
// speedup vs baseline: 1.8139x; 1.0400x over previous
#include <cuda_runtime.h>
#include <cuda_fp16.h>
#include <cstdint>

#define BB 16
#define NN 576
#define DD 1024
#define HH 16
#define HD 64

// ---------------- scratch (static device globals; no allocation) ----------------
__device__ __align__(16) __half g_xh[(long)BB * NN * DD];        // x fp16
__device__ __align__(16) __half g_qkh[(long)BB * NN * 2 * DD];   // qk hi fp16
__device__ __align__(16) __half g_qkl[(long)BB * NN * 2 * DD];   // qk lo fp16
__device__ __align__(16) __half g_vh[(long)BB * NN * DD];        // v fp16
__device__ __align__(16) __half g_oh[(long)BB * NN * DD];        // o fp16
__device__ __align__(16) __half g_posh[(long)HH * NN * NN];      // pos fp16
__device__ __align__(16) __half g_wtqk[(long)2 * DD * DD];       // W_qk^T fp16 [n][k]
__device__ __align__(16) __half g_wtv[(long)DD * DD];
__device__ __align__(16) __half g_wtp[(long)DD * DD];

// ---------------- helpers ------------------------------------------------------
__device__ __forceinline__ void mma_fp16(float& d0, float& d1, float& d2, float& d3,
                                         unsigned a0, unsigned a1, unsigned a2, unsigned a3,
                                         unsigned b0, unsigned b1) {
    asm volatile(
        "mma.sync.aligned.m16n8k16.row.col.f32.f16.f16.f32 "
        "{%0,%1,%2,%3}, {%4,%5,%6,%7}, {%8,%9}, {%0,%1,%2,%3};\n"
        : "+f"(d0), "+f"(d1), "+f"(d2), "+f"(d3)
        : "r"(a0), "r"(a1), "r"(a2), "r"(a3), "r"(b0), "r"(b1));
}

__device__ __forceinline__ unsigned packh2(__half x, __half y) {
    __half2 t;
    t.x = x; t.y = y;
    return *reinterpret_cast<unsigned*>(&t);
}

__device__ __forceinline__ unsigned pack2f(float x, float y) {
    return packh2(__float2half_rn(x), __float2half_rn(y));
}

__device__ __forceinline__ void split2h(float x, float y, unsigned& hi, unsigned& lo) {
    __half hx = __float2half_rn(x), hy = __float2half_rn(y);
    hi = packh2(hx, hy);
    lo = packh2(__float2half_rn(x - __half2float(hx)),
                __float2half_rn(y - __half2float(hy)));
}

// ---------------- prep: fp32 -> fp16 convert -----------------------------------
__global__ void cvt_half_k(const float* __restrict__ in, __half* __restrict__ out, int n) {
    int i = (blockIdx.x * 256 + threadIdx.x) * 4;
    if (i >= n) return;
    float4 a = *(const float4*)(in + i);
    __half2* o2 = (__half2*)(out + i);
    o2[0] = __floats2half2_rn(a.x, a.y);
    o2[1] = __floats2half2_rn(a.z, a.w);
}

// ---------------- prep: W [K][N] fp32 -> W^T [N][K] fp16 -----------------------
__global__ void transpose_w(const float* __restrict__ W, __half* __restrict__ Wt,
                            int K, int N) {
    __shared__ float t[32][33];
    const int k0 = blockIdx.y * 32, n0 = blockIdx.x * 32;
    const int tx = threadIdx.x, ty = threadIdx.y;
#pragma unroll
    for (int i = 0; i < 32; i += 8)
        t[ty + i][tx] = W[(long)(k0 + ty + i) * N + n0 + tx];
    __syncthreads();
#pragma unroll
    for (int i = 0; i < 32; i += 8)
        Wt[(long)(n0 + ty + i) * K + k0 + tx] = __float2half_rn(t[tx][ty + i]);
}

// ---------------- fp16 GEMM: C = A[M,K] @ Bt[N,K]^T ----------------------------
// 128x128 tile, K-chunk 32. 8 warps = 2m x 4n. A,B fp16 in gmem -> raw uint4
// smem stores (no conversion). CMODE: 0=fp32(+bias), 1=fp16, 2=fp16 hi/lo split.
#define GKP 20
#define G_WORDS (128 * GKP)
#define G_STG (2 * G_WORDS)
#define GS_SMEM (2 * G_STG * 4)               // 40960 B

template <int CMODE, bool BIAS>
__global__ __launch_bounds__(256, 2) void gemm_h(const __half* __restrict__ A,
                                                 const __half* __restrict__ Bt,
                                                 const float* __restrict__ bias,
                                                 void* __restrict__ C0,
                                                 __half* __restrict__ Cl,
                                                 int M, int K, int N) {
    extern __shared__ unsigned gsm[];
    const int tid = threadIdx.x;
    const int warp = tid >> 5, lane = tid & 31;
    const int wm = (warp & 1) * 64, wn = (warp >> 1) * 32;
    const int gp = lane >> 2, tg = lane & 3;
    const int bm = blockIdx.y * 128, bn = blockIdx.x * 128;

    float acc[4][4][4];
#pragma unroll
    for (int i = 0; i < 4; i++)
#pragma unroll
        for (int j = 0; j < 4; j++)
#pragma unroll
            for (int r = 0; r < 4; r++) acc[i][j][r] = 0.0f;

    uint4 aS[2], bS[2];
    const __half* Ab = A + (long)bm * K;
    const __half* Bb = Bt + (long)bn * K;

#define G_LOAD(k0)                                                              \
    {                                                                           \
        _Pragma("unroll") for (int i = 0; i < 2; i++) {                         \
            int idx = tid + 256 * i;                                            \
            int row = idx >> 2, seg = idx & 3;                                  \
            aS[i] = *(const uint4*)(Ab + (long)row * K + (k0) + seg * 8);       \
            bS[i] = *(const uint4*)(Bb + (long)row * K + (k0) + seg * 8);       \
        }                                                                       \
    }

#define G_STORE(s)                                                              \
    {                                                                           \
        unsigned* Ad = gsm + (s) * G_STG;                                       \
        unsigned* Bd = Ad + G_WORDS;                                            \
        _Pragma("unroll") for (int i = 0; i < 2; i++) {                         \
            int idx = tid + 256 * i;                                            \
            int row = idx >> 2, seg = idx & 3;                                  \
            *(uint4*)(Ad + row * GKP + seg * 4) = aS[i];                        \
            *(uint4*)(Bd + row * GKP + seg * 4) = bS[i];                        \
        }                                                                       \
    }

#define G_COMPUTE(s)                                                            \
    {                                                                           \
        const unsigned* Ar = gsm + (s) * G_STG;                                 \
        const unsigned* Br = Ar + G_WORDS;                                      \
        _Pragma("unroll") for (int st = 0; st < 2; st++) {                      \
            const int w0 = st * 8 + tg;                                         \
            unsigned af[4][4];                                                  \
            _Pragma("unroll") for (int ma = 0; ma < 4; ma++) {                  \
                const int r = (wm + ma * 16 + gp) * GKP;                        \
                af[ma][0] = Ar[r + w0];                                         \
                af[ma][1] = Ar[r + 8 * GKP + w0];                               \
                af[ma][2] = Ar[r + w0 + 4];                                     \
                af[ma][3] = Ar[r + 8 * GKP + w0 + 4];                           \
            }                                                                   \
            _Pragma("unroll") for (int nb = 0; nb < 4; nb++) {                  \
                const int nc = (wn + nb * 8 + gp) * GKP;                        \
                unsigned b0 = Br[nc + w0], b1 = Br[nc + w0 + 4];                \
                _Pragma("unroll") for (int ma = 0; ma < 4; ma++)                \
                    mma_fp16(acc[ma][nb][0], acc[ma][nb][1], acc[ma][nb][2],    \
                             acc[ma][nb][3], af[ma][0], af[ma][1], af[ma][2],   \
                             af[ma][3], b0, b1);                                \
            }                                                                   \
        }                                                                       \
    }

    int s = 0;
    G_LOAD(0);
    G_STORE(0);
    __syncthreads();

    for (int k0 = 32; k0 < K; k0 += 32) {
        G_LOAD(k0);
        G_COMPUTE(s);
        G_STORE(s ^ 1);
        s ^= 1;
        __syncthreads();
    }
    G_COMPUTE(s);

#pragma unroll
    for (int ma = 0; ma < 4; ma++) {
        const long r0 = bm + wm + ma * 16 + gp;
        const long r1 = r0 + 8;
#pragma unroll
        for (int nb = 0; nb < 4; nb++) {
            const int col = bn + wn + nb * 8 + tg * 2;
            if (CMODE == 0) {
                float* C = (float*)C0;
                float2 v0 = make_float2(acc[ma][nb][0], acc[ma][nb][1]);
                float2 v1 = make_float2(acc[ma][nb][2], acc[ma][nb][3]);
                if (BIAS) {
                    const float bb0 = __ldg(bias + col), bb1 = __ldg(bias + col + 1);
                    v0.x += bb0; v0.y += bb1;
                    v1.x += bb0; v1.y += bb1;
                }
                *(float2*)(C + r0 * N + col) = v0;
                *(float2*)(C + r1 * N + col) = v1;
            } else if (CMODE == 1) {
                __half* C = (__half*)C0;
                *(unsigned*)(C + r0 * N + col) = pack2f(acc[ma][nb][0], acc[ma][nb][1]);
                *(unsigned*)(C + r1 * N + col) = pack2f(acc[ma][nb][2], acc[ma][nb][3]);
            } else {
                __half* Ch = (__half*)C0;
                unsigned hh, ll;
                split2h(acc[ma][nb][0], acc[ma][nb][1], hh, ll);
                *(unsigned*)(Ch + r0 * N + col) = hh;
                *(unsigned*)(Cl + r0 * N + col) = ll;
                split2h(acc[ma][nb][2], acc[ma][nb][3], hh, ll);
                *(unsigned*)(Ch + r1 * N + col) = hh;
                *(unsigned*)(Cl + r1 * N + col) = ll;
            }
        }
    }
#undef G_LOAD
#undef G_STORE
#undef G_COMPUTE
}

// ---------------- positional softmax -> fp16 -----------------------------------
__global__ __launch_bounds__(256) void pos_kernel(const float* __restrict__ rel,
                                                  const float* __restrict__ Wp,
                                                  const float* __restrict__ bp,
                                                  __half* __restrict__ pos) {
    const int n = blockIdx.x, h = blockIdx.y, tid = threadIdx.x;
    __shared__ float red[8];
    __shared__ float bcv;
    const float w0 = Wp[h], w1 = Wp[HH + h], w2 = Wp[2 * HH + h], bb = bp[h];
    const float* r = rel + (long)n * NN * 3;

    float s0, s1, s2 = -1e30f;
    {
        const float* p = r + tid * 3;
        s0 = p[0] * w0 + p[1] * w1 + p[2] * w2 + bb;
        p = r + (tid + 256) * 3;
        s1 = p[0] * w0 + p[1] * w1 + p[2] * w2 + bb;
        if (tid < 64) {
            p = r + (tid + 512) * 3;
            s2 = p[0] * w0 + p[1] * w1 + p[2] * w2 + bb;
        }
    }
    float mx = fmaxf(fmaxf(s0, s1), s2);
#pragma unroll
    for (int o = 16; o; o >>= 1) mx = fmaxf(mx, __shfl_xor_sync(~0u, mx, o));
    if ((tid & 31) == 0) red[tid >> 5] = mx;
    __syncthreads();
    if (tid == 0) {
        float m = red[0];
        for (int i = 1; i < 8; i++) m = fmaxf(m, red[i]);
        bcv = m;
    }
    __syncthreads();
    mx = bcv;
    float e0 = expf(s0 - mx), e1 = expf(s1 - mx);
    float e2 = (tid < 64) ? expf(s2 - mx) : 0.0f;
    float sum = e0 + e1 + e2;
#pragma unroll
    for (int o = 16; o; o >>= 1) sum += __shfl_xor_sync(~0u, sum, o);
    __syncthreads();
    if ((tid & 31) == 0) red[tid >> 5] = sum;
    __syncthreads();
    if (tid == 0) {
        float s = 0.f;
        for (int i = 0; i < 8; i++) s += red[i];
        bcv = 1.0f / s;
    }
    __syncthreads();
    const float inv = bcv;
    __half* out = pos + ((long)h * NN + n) * NN;
    out[tid] = __float2half_rn(e0 * inv);
    out[tid + 256] = __float2half_rn(e1 * inv);
    if (tid < 64) out[tid + 512] = __float2half_rn(e2 * inv);
}

// ---------------- fused one-pass attention -------------------------------------
// q,k tiles: pre-split hi/lo fp16 loaded raw (uint4). pos fp16 raw. v fp16
// transposed in-kernel. S = 3-term split-fp16; PV plain fp16 (identity P pack).
#define PB 36
#define FA_SMEM (6 * 64 * PB * 4)   // 55296 B

__global__ __launch_bounds__(256, 2) void fused_attn(
    const __half* __restrict__ qkh, const __half* __restrict__ qkl,
    const __half* __restrict__ v, const __half* __restrict__ pos,
    const float* __restrict__ gating, __half* __restrict__ o) {
    extern __shared__ unsigned smem[];
    unsigned* qs_h = smem;                 // [64][36] fp16x2 d-pairs
    unsigned* qs_l = qs_h + 64 * PB;
    unsigned* ks_h = qs_l + 64 * PB;       // [64 seq][36]
    unsigned* ks_l = ks_h + 64 * PB;
    unsigned* ps   = ks_l + 64 * PB;       // [64 qrow][36] fp16x2 seq-pairs
    unsigned* vt   = ps + 64 * PB;         // [64 d][36]  (V^T)

    const int tid = threadIdx.x, warp = tid >> 5, lane = tid & 31;
    const int gp = lane >> 2, tg = lane & 3;
    const int wm = (warp & 3) * 16;
    const int wh = warp >> 2;
    const int n0 = blockIdx.x * 64;
    const int b = blockIdx.y >> 4, h = blockIdx.y & 15;

    const __half* qhb = qkh + (long)b * NN * 2048 + (long)n0 * 2048 + h * 64;
    const __half* qlb = qkl + (long)b * NN * 2048 + (long)n0 * 2048 + h * 64;
    const __half* khb = qkh + (long)b * NN * 2048 + 1024 + h * 64;
    const __half* klb = qkl + (long)b * NN * 2048 + 1024 + h * 64;
    const __half* pbase = pos + ((long)h * NN + n0) * NN;

    // ---- load q tile (raw pre-split) ----
    {
        int idx = tid;
#pragma unroll
        for (int i = 0; i < 2; i++, idx += 256) {
            int r = idx >> 3, seg = idx & 7;
            *(uint4*)(qs_h + r * PB + seg * 4) = *(const uint4*)(qhb + (long)r * 2048 + seg * 8);
            *(uint4*)(qs_l + r * PB + seg * 4) = *(const uint4*)(qlb + (long)r * 2048 + seg * 8);
        }
    }

    float Oc[8][4], Op[8][4];
#pragma unroll
    for (int i = 0; i < 8; i++)
#pragma unroll
        for (int j = 0; j < 4; j++) { Oc[i][j] = 0.0f; Op[i][j] = 0.0f; }
    float l0 = 0.0f, l1 = 0.0f;
    const float scale = 0.125f;

    const int vd = tid & 63, vkg = tid >> 6;

    for (int m0 = 0; m0 < NN; m0 += 64) {
        __syncthreads();
        {
            int idx = tid;
#pragma unroll
            for (int i = 0; i < 2; i++, idx += 256) {
                int r = idx >> 3, seg = idx & 7;
                *(uint4*)(ks_h + r * PB + seg * 4) =
                    *(const uint4*)(khb + (long)(m0 + r) * 2048 + seg * 8);
                *(uint4*)(ks_l + r * PB + seg * 4) =
                    *(const uint4*)(klb + (long)(m0 + r) * 2048 + seg * 8);
                *(uint4*)(ps + r * PB + seg * 4) =
                    *(const uint4*)(pbase + (long)r * NN + m0 + seg * 8);
            }
            // v^T: thread gathers 16 seq-values for one d column
            const __half* vp = v + ((long)b * NN + m0 + vkg * 16) * DD + h * 64 + vd;
            __half vv[16];
#pragma unroll
            for (int j = 0; j < 16; j++) vv[j] = vp[(long)j * DD];
#pragma unroll
            for (int i = 0; i < 8; i++)
                vt[vd * PB + vkg * 8 + i] = packh2(vv[2 * i], vv[2 * i + 1]);
        }
        __syncthreads();

        // ---- S = q @ k^T over warp's 16x32 slice (split-fp16, 3 terms) ----
        float p[4][4];
#pragma unroll
        for (int i = 0; i < 4; i++)
#pragma unroll
            for (int j = 0; j < 4; j++) p[i][j] = 0.0f;

        const int rowA = (wm + gp) * PB;
#pragma unroll
        for (int kc = 0; kc < 4; kc++) {
            const int d2 = kc * 8 + tg;
            unsigned ah0 = qs_h[rowA + d2];
            unsigned ah1 = qs_h[rowA + 8 * PB + d2];
            unsigned ah2 = qs_h[rowA + d2 + 4];
            unsigned ah3 = qs_h[rowA + 8 * PB + d2 + 4];
            unsigned al0 = qs_l[rowA + d2];
            unsigned al1 = qs_l[rowA + 8 * PB + d2];
            unsigned al2 = qs_l[rowA + d2 + 4];
            unsigned al3 = qs_l[rowA + 8 * PB + d2 + 4];
#pragma unroll
            for (int na = 0; na < 4; na++) {
                const int rowB = (wh * 32 + na * 8 + gp) * PB;
                unsigned bh0 = ks_h[rowB + d2];
                unsigned bh1 = ks_h[rowB + d2 + 4];
                unsigned bl0 = ks_l[rowB + d2];
                unsigned bl1 = ks_l[rowB + d2 + 4];
                mma_fp16(p[na][0], p[na][1], p[na][2], p[na][3],
                         ah0, ah1, ah2, ah3, bh0, bh1);
                mma_fp16(p[na][0], p[na][1], p[na][2], p[na][3],
                         ah0, ah1, ah2, ah3, bl0, bl1);
                mma_fp16(p[na][0], p[na][1], p[na][2], p[na][3],
                         al0, al1, al2, al3, bh0, bh1);
            }
        }

        // ---- exp (no max-sub), row sums ----
#pragma unroll
        for (int na = 0; na < 4; na++) {
            p[na][0] = __expf(p[na][0] * scale);
            p[na][1] = __expf(p[na][1] * scale);
            p[na][2] = __expf(p[na][2] * scale);
            p[na][3] = __expf(p[na][3] * scale);
            l0 += p[na][0] + p[na][1];
            l1 += p[na][2] + p[na][3];
        }

        // ---- O_c += P@v, O_p += pos@v (plain fp16 k16) ----
#pragma unroll
        for (int s = 0; s < 2; s++) {
            unsigned Pa0 = pack2f(p[2 * s][0],     p[2 * s][1]);
            unsigned Pa1 = pack2f(p[2 * s][2],     p[2 * s][3]);
            unsigned Pa2 = pack2f(p[2 * s + 1][0], p[2 * s + 1][1]);
            unsigned Pa3 = pack2f(p[2 * s + 1][2], p[2 * s + 1][3]);

            const int wb = wh * 16 + s * 8 + tg;
            const int rA = (wm + gp) * PB + wb;
            unsigned pa0 = ps[rA],     pa1 = ps[rA + 8 * PB];
            unsigned pa2 = ps[rA + 4], pa3 = ps[rA + 8 * PB + 4];
#pragma unroll
            for (int nv = 0; nv < 8; nv++) {
                const int rB = (nv * 8 + gp) * PB + wb;
                unsigned b0 = vt[rB], b1 = vt[rB + 4];
                mma_fp16(Oc[nv][0], Oc[nv][1], Oc[nv][2], Oc[nv][3],
                         Pa0, Pa1, Pa2, Pa3, b0, b1);
                mma_fp16(Op[nv][0], Op[nv][1], Op[nv][2], Op[nv][3],
                         pa0, pa1, pa2, pa3, b0, b1);
            }
        }
    }

    // ---- reduce row-sums within tg group ----
    l0 += __shfl_xor_sync(~0u, l0, 1); l0 += __shfl_xor_sync(~0u, l0, 2);
    l1 += __shfl_xor_sync(~0u, l1, 1); l1 += __shfl_xor_sync(~0u, l1, 2);

    // ---- combine warp-half partials via smem scratch ----
    float* sOc = (float*)smem;          // [64][65]
    float* sOp = sOc + 64 * 65;
    float* slb = sOp + 64 * 65;
    __syncthreads();
    if (wh == 1) {
#pragma unroll
        for (int nv = 0; nv < 8; nv++) {
            const int base = (wm + gp) * 65 + nv * 8 + 2 * tg;
            sOc[base]              = Oc[nv][0];
            sOc[base + 1]          = Oc[nv][1];
            sOc[base + 8 * 65]     = Oc[nv][2];
            sOc[base + 8 * 65 + 1] = Oc[nv][3];
            sOp[base]              = Op[nv][0];
            sOp[base + 1]          = Op[nv][1];
            sOp[base + 8 * 65]     = Op[nv][2];
            sOp[base + 8 * 65 + 1] = Op[nv][3];
        }
        slb[wm + gp] = l0;
        slb[wm + gp + 8] = l1;
    }
    __syncthreads();
    if (wh == 0) {
        const float g = 1.0f / (1.0f + __expf(-gating[h]));
        const float og = 1.0f - g;
        const float lt0 = l0 + slb[wm + gp];
        const float lt1 = l1 + slb[wm + gp + 8];
        const float c0 = og / lt0, c1 = og / lt1;
        const long row = n0 + wm + gp;
        __half* dst0 = o + ((long)b * NN + row) * DD + h * 64;
#pragma unroll
        for (int nv = 0; nv < 8; nv++) {
            const int base = (wm + gp) * 65 + nv * 8 + 2 * tg;
            float oc0 = Oc[nv][0] + sOc[base];
            float oc1 = Oc[nv][1] + sOc[base + 1];
            float oc2 = Oc[nv][2] + sOc[base + 8 * 65];
            float oc3 = Oc[nv][3] + sOc[base + 8 * 65 + 1];
            float op0 = Op[nv][0] + sOp[base];
            float op1 = Op[nv][1] + sOp[base + 1];
            float op2 = Op[nv][2] + sOp[base + 8 * 65];
            float op3 = Op[nv][3] + sOp[base + 8 * 65 + 1];
            __half* dst = dst0 + nv * 8 + 2 * tg;
            *(unsigned*)dst = pack2f(c0 * oc0 + g * op0, c0 * oc1 + g * op1);
            *(unsigned*)(dst + 8L * DD) = pack2f(c1 * oc2 + g * op2, c1 * oc3 + g * op3);
        }
    }
}

// ---------------- launch ----------------
extern "C" void kernel_launch(void* const* d_in, const int* in_sizes, int n_in,
                              void* d_out, int out_size) {
    const float* x      = (const float*)d_in[0];
    const float* W_qk   = (const float*)d_in[1];
    const float* W_v    = (const float*)d_in[2];
    const float* W_proj = (const float*)d_in[3];
    const float* b_proj = (const float*)d_in[4];
    const float* W_pos  = (const float*)d_in[5];
    const float* b_pos  = (const float*)d_in[6];
    const float* gating = (const float*)d_in[7];
    const float* rel    = (const float*)d_in[8];
    float* out = (float*)d_out;

    __half *xh, *qkh, *qkl, *vh, *oh, *posh, *wtqk, *wtv, *wtp;
    cudaGetSymbolAddress((void**)&xh,   g_xh);
    cudaGetSymbolAddress((void**)&qkh,  g_qkh);
    cudaGetSymbolAddress((void**)&qkl,  g_qkl);
    cudaGetSymbolAddress((void**)&vh,   g_vh);
    cudaGetSymbolAddress((void**)&oh,   g_oh);
    cudaGetSymbolAddress((void**)&posh, g_posh);
    cudaGetSymbolAddress((void**)&wtqk, g_wtqk);
    cudaGetSymbolAddress((void**)&wtv,  g_wtv);
    cudaGetSymbolAddress((void**)&wtp,  g_wtp);

    cudaFuncSetAttribute(gemm_h<0, true>,  cudaFuncAttributeMaxDynamicSharedMemorySize, GS_SMEM);
    cudaFuncSetAttribute(gemm_h<1, false>, cudaFuncAttributeMaxDynamicSharedMemorySize, GS_SMEM);
    cudaFuncSetAttribute(gemm_h<2, false>, cudaFuncAttributeMaxDynamicSharedMemorySize, GS_SMEM);
    cudaFuncSetAttribute(fused_attn, cudaFuncAttributeMaxDynamicSharedMemorySize, FA_SMEM);

    const int M = BB * NN;  // 9216

    // prep: x -> fp16; W -> W^T fp16; pos softmax -> fp16
    cvt_half_k<<<(M * DD / 4 + 255) / 256, 256>>>(x, xh, M * DD);
    transpose_w<<<dim3(2 * DD / 32, DD / 32), dim3(32, 8)>>>(W_qk, wtqk, DD, 2 * DD);
    transpose_w<<<dim3(DD / 32, DD / 32), dim3(32, 8)>>>(W_v, wtv, DD, DD);
    transpose_w<<<dim3(DD / 32, DD / 32), dim3(32, 8)>>>(W_proj, wtp, DD, DD);
    pos_kernel<<<dim3(NN, HH), 256>>>(rel, W_pos, b_pos, posh);

    // qk = x @ W_qk  (pre-split hi/lo fp16)
    gemm_h<2, false><<<dim3(2 * DD / 128, M / 128), 256, GS_SMEM>>>(
        xh, wtqk, nullptr, qkh, qkl, M, DD, 2 * DD);
    // v = x @ W_v  (fp16)
    gemm_h<1, false><<<dim3(DD / 128, M / 128), 256, GS_SMEM>>>(
        xh, wtv, nullptr, vh, nullptr, M, DD, DD);
    // fused one-pass attention -> o fp16
    fused_attn<<<dim3(NN / 64, BB * HH), 256, FA_SMEM>>>(qkh, qkl, vh, posh, gating, oh);
    // out = o @ W_proj + b_proj  (fp32 + bias)
    gemm_h<0, true><<<dim3(DD / 128, M / 128), 256, GS_SMEM>>>(
        oh, wtp, b_proj, out, nullptr, M, DD, DD);
}

// round 12
// speedup vs baseline: 2.0050x; 1.1054x over previous
#include <cuda_runtime.h>
#include <cuda_fp16.h>
#include <cstdint>

#define BB 16
#define NN 576
#define DD 1024
#define HH 16
#define HD 64

// ---------------- scratch (static device globals; no allocation) ----------------
__device__ __align__(16) __half g_xh[(long)BB * NN * DD];        // x fp16
__device__ __align__(16) __half g_qkh[(long)BB * NN * 2 * DD];   // qk hi fp16
__device__ __align__(16) __half g_qkl[(long)BB * NN * 2 * DD];   // qk lo fp16
__device__ __align__(16) __half g_vh[(long)BB * NN * DD];        // v fp16
__device__ __align__(16) __half g_oh[(long)BB * NN * DD];        // o fp16
__device__ __align__(16) __half g_posh[(long)HH * NN * NN];      // pos fp16
__device__ __align__(16) __half g_wtqk[(long)2 * DD * DD];       // W_qk^T fp16 [n][k]
__device__ __align__(16) __half g_wtv[(long)DD * DD];
__device__ __align__(16) __half g_wtp[(long)DD * DD];

// ---------------- helpers ------------------------------------------------------
__device__ __forceinline__ void mma_fp16(float& d0, float& d1, float& d2, float& d3,
                                         unsigned a0, unsigned a1, unsigned a2, unsigned a3,
                                         unsigned b0, unsigned b1) {
    asm volatile(
        "mma.sync.aligned.m16n8k16.row.col.f32.f16.f16.f32 "
        "{%0,%1,%2,%3}, {%4,%5,%6,%7}, {%8,%9}, {%0,%1,%2,%3};\n"
        : "+f"(d0), "+f"(d1), "+f"(d2), "+f"(d3)
        : "r"(a0), "r"(a1), "r"(a2), "r"(a3), "r"(b0), "r"(b1));
}

__device__ __forceinline__ void ldsm_x4(unsigned& r0, unsigned& r1, unsigned& r2,
                                        unsigned& r3, unsigned addr) {
    asm volatile("ldmatrix.sync.aligned.m8n8.x4.shared.b16 {%0,%1,%2,%3}, [%4];"
                 : "=r"(r0), "=r"(r1), "=r"(r2), "=r"(r3) : "r"(addr));
}

__device__ __forceinline__ unsigned packh2(__half x, __half y) {
    __half2 t;
    t.x = x; t.y = y;
    return *reinterpret_cast<unsigned*>(&t);
}

__device__ __forceinline__ unsigned pack2f(float x, float y) {
    return packh2(__float2half_rn(x), __float2half_rn(y));
}

__device__ __forceinline__ void split2h(float x, float y, unsigned& hi, unsigned& lo) {
    __half hx = __float2half_rn(x), hy = __float2half_rn(y);
    hi = packh2(hx, hy);
    lo = packh2(__float2half_rn(x - __half2float(hx)),
                __float2half_rn(y - __half2float(hy)));
}

// ---------------- prep: fp32 -> fp16 convert -----------------------------------
__global__ void cvt_half_k(const float* __restrict__ in, __half* __restrict__ out, int n) {
    int i = (blockIdx.x * 256 + threadIdx.x) * 4;
    if (i >= n) return;
    float4 a = *(const float4*)(in + i);
    __half2* o2 = (__half2*)(out + i);
    o2[0] = __floats2half2_rn(a.x, a.y);
    o2[1] = __floats2half2_rn(a.z, a.w);
}

// ---------------- prep: W [K][N] fp32 -> W^T [N][K] fp16 -----------------------
__global__ void transpose_w(const float* __restrict__ W, __half* __restrict__ Wt,
                            int K, int N) {
    __shared__ float t[32][33];
    const int k0 = blockIdx.y * 32, n0 = blockIdx.x * 32;
    const int tx = threadIdx.x, ty = threadIdx.y;
#pragma unroll
    for (int i = 0; i < 32; i += 8)
        t[ty + i][tx] = W[(long)(k0 + ty + i) * N + n0 + tx];
    __syncthreads();
#pragma unroll
    for (int i = 0; i < 32; i += 8)
        Wt[(long)(n0 + ty + i) * K + k0 + tx] = __float2half_rn(t[tx][ty + i]);
}

// ---------------- fp16 GEMM: C = A[M,K] @ Bt[N,K]^T ----------------------------
// 128x128 tile, K-chunk 32. 8 warps = 2m x 4n. ldmatrix fragment loads.
// CMODE: 0=fp32(+bias), 1=fp16, 2=fp16 hi/lo split.
#define GKP 20
#define G_WORDS (128 * GKP)
#define G_STG (2 * G_WORDS)
#define GS_SMEM (2 * G_STG * 4)               // 40960 B

template <int CMODE, bool BIAS>
__global__ __launch_bounds__(256, 2) void gemm_h(const __half* __restrict__ A,
                                                 const __half* __restrict__ Bt,
                                                 const float* __restrict__ bias,
                                                 void* __restrict__ C0,
                                                 __half* __restrict__ Cl,
                                                 int M, int K, int N) {
    extern __shared__ unsigned gsm[];
    const unsigned smA = (unsigned)__cvta_generic_to_shared(gsm);
    const int tid = threadIdx.x;
    const int warp = tid >> 5, lane = tid & 31;
    const int wm = (warp & 1) * 64, wn = (warp >> 1) * 32;
    const int gp = lane >> 2, tg = lane & 3;
    const int bm = blockIdx.y * 128, bn = blockIdx.x * 128;

    float acc[4][4][4];
#pragma unroll
    for (int i = 0; i < 4; i++)
#pragma unroll
        for (int j = 0; j < 4; j++)
#pragma unroll
            for (int r = 0; r < 4; r++) acc[i][j][r] = 0.0f;

    uint4 aS[2], bS[2];
    const __half* Ab = A + (long)bm * K;
    const __half* Bb = Bt + (long)bn * K;

    // ldmatrix lane-address components (constant over loop)
    const int lm15 = lane & 15, lh = (lane >> 4) & 1, lq = (lane >> 3) & 1, l7 = lane & 7;

#define G_LOAD(k0)                                                              \
    {                                                                           \
        _Pragma("unroll") for (int i = 0; i < 2; i++) {                         \
            int idx = tid + 256 * i;                                            \
            int row = idx >> 2, seg = idx & 3;                                  \
            aS[i] = *(const uint4*)(Ab + (long)row * K + (k0) + seg * 8);       \
            bS[i] = *(const uint4*)(Bb + (long)row * K + (k0) + seg * 8);       \
        }                                                                       \
    }

#define G_STORE(s)                                                              \
    {                                                                           \
        unsigned* Ad = gsm + (s) * G_STG;                                       \
        unsigned* Bd = Ad + G_WORDS;                                            \
        _Pragma("unroll") for (int i = 0; i < 2; i++) {                         \
            int idx = tid + 256 * i;                                            \
            int row = idx >> 2, seg = idx & 3;                                  \
            *(uint4*)(Ad + row * GKP + seg * 4) = aS[i];                        \
            *(uint4*)(Bd + row * GKP + seg * 4) = bS[i];                        \
        }                                                                       \
    }

#define G_COMPUTE(s)                                                            \
    {                                                                           \
        const unsigned aBase = smA + (s) * G_STG * 4;                           \
        const unsigned bBase = aBase + G_WORDS * 4;                             \
        _Pragma("unroll") for (int st = 0; st < 2; st++) {                      \
            unsigned af[4][4];                                                  \
            _Pragma("unroll") for (int ma = 0; ma < 4; ma++)                    \
                ldsm_x4(af[ma][0], af[ma][1], af[ma][2], af[ma][3],             \
                        aBase + (((wm + ma * 16 + lm15) * GKP + st * 8 +        \
                                  lh * 4) << 2));                               \
            unsigned bf[4][2];                                                  \
            _Pragma("unroll") for (int p2 = 0; p2 < 2; p2++)                    \
                ldsm_x4(bf[2 * p2][0], bf[2 * p2][1], bf[2 * p2 + 1][0],        \
                        bf[2 * p2 + 1][1],                                      \
                        bBase + (((wn + p2 * 16 + lh * 8 + l7) * GKP +          \
                                  st * 8 + lq * 4) << 2));                      \
            _Pragma("unroll") for (int nb = 0; nb < 4; nb++)                    \
                _Pragma("unroll") for (int ma = 0; ma < 4; ma++)                \
                    mma_fp16(acc[ma][nb][0], acc[ma][nb][1], acc[ma][nb][2],    \
                             acc[ma][nb][3], af[ma][0], af[ma][1], af[ma][2],   \
                             af[ma][3], bf[nb][0], bf[nb][1]);                  \
        }                                                                       \
    }

    int s = 0;
    G_LOAD(0);
    G_STORE(0);
    __syncthreads();

    for (int k0 = 32; k0 < K; k0 += 32) {
        G_LOAD(k0);
        G_COMPUTE(s);
        G_STORE(s ^ 1);
        s ^= 1;
        __syncthreads();
    }
    G_COMPUTE(s);

#pragma unroll
    for (int ma = 0; ma < 4; ma++) {
        const long r0 = bm + wm + ma * 16 + gp;
        const long r1 = r0 + 8;
#pragma unroll
        for (int nb = 0; nb < 4; nb++) {
            const int col = bn + wn + nb * 8 + tg * 2;
            if (CMODE == 0) {
                float* C = (float*)C0;
                float2 v0 = make_float2(acc[ma][nb][0], acc[ma][nb][1]);
                float2 v1 = make_float2(acc[ma][nb][2], acc[ma][nb][3]);
                if (BIAS) {
                    const float bb0 = __ldg(bias + col), bb1 = __ldg(bias + col + 1);
                    v0.x += bb0; v0.y += bb1;
                    v1.x += bb0; v1.y += bb1;
                }
                *(float2*)(C + r0 * N + col) = v0;
                *(float2*)(C + r1 * N + col) = v1;
            } else if (CMODE == 1) {
                __half* C = (__half*)C0;
                *(unsigned*)(C + r0 * N + col) = pack2f(acc[ma][nb][0], acc[ma][nb][1]);
                *(unsigned*)(C + r1 * N + col) = pack2f(acc[ma][nb][2], acc[ma][nb][3]);
            } else {
                __half* Ch = (__half*)C0;
                unsigned hh, ll;
                split2h(acc[ma][nb][0], acc[ma][nb][1], hh, ll);
                *(unsigned*)(Ch + r0 * N + col) = hh;
                *(unsigned*)(Cl + r0 * N + col) = ll;
                split2h(acc[ma][nb][2], acc[ma][nb][3], hh, ll);
                *(unsigned*)(Ch + r1 * N + col) = hh;
                *(unsigned*)(Cl + r1 * N + col) = ll;
            }
        }
    }
#undef G_LOAD
#undef G_STORE
#undef G_COMPUTE
}

// ---------------- positional softmax -> fp16 (one block per row, loop heads) ---
__global__ __launch_bounds__(256) void pos_kernel(const float* __restrict__ rel,
                                                  const float* __restrict__ Wp,
                                                  const float* __restrict__ bp,
                                                  __half* __restrict__ pos) {
    const int n = blockIdx.x, tid = threadIdx.x;
    __shared__ float red[8];
    __shared__ float bcv;
    const float* r = rel + (long)n * NN * 3;

    // hold this row's rel coords in registers (cols tid, tid+256, tid+512)
    const float r0x = r[tid * 3], r0y = r[tid * 3 + 1], r0z = r[tid * 3 + 2];
    const float r1x = r[(tid + 256) * 3], r1y = r[(tid + 256) * 3 + 1],
                r1z = r[(tid + 256) * 3 + 2];
    float r2x = 0, r2y = 0, r2z = 0;
    if (tid < 64) {
        r2x = r[(tid + 512) * 3]; r2y = r[(tid + 512) * 3 + 1];
        r2z = r[(tid + 512) * 3 + 2];
    }

    for (int h = 0; h < HH; h++) {
        const float w0 = Wp[h], w1 = Wp[HH + h], w2 = Wp[2 * HH + h], bb = bp[h];
        float s0 = r0x * w0 + r0y * w1 + r0z * w2 + bb;
        float s1 = r1x * w0 + r1y * w1 + r1z * w2 + bb;
        float s2 = (tid < 64) ? (r2x * w0 + r2y * w1 + r2z * w2 + bb) : -1e30f;

        float mx = fmaxf(fmaxf(s0, s1), s2);
#pragma unroll
        for (int o = 16; o; o >>= 1) mx = fmaxf(mx, __shfl_xor_sync(~0u, mx, o));
        if ((tid & 31) == 0) red[tid >> 5] = mx;
        __syncthreads();
        if (tid == 0) {
            float m = red[0];
            for (int i = 1; i < 8; i++) m = fmaxf(m, red[i]);
            bcv = m;
        }
        __syncthreads();
        mx = bcv;
        float e0 = expf(s0 - mx), e1 = expf(s1 - mx);
        float e2 = (tid < 64) ? expf(s2 - mx) : 0.0f;
        float sum = e0 + e1 + e2;
#pragma unroll
        for (int o = 16; o; o >>= 1) sum += __shfl_xor_sync(~0u, sum, o);
        if ((tid & 31) == 0) red[tid >> 5] = sum;
        __syncthreads();
        if (tid == 0) {
            float s = 0.f;
            for (int i = 0; i < 8; i++) s += red[i];
            bcv = 1.0f / s;
        }
        __syncthreads();
        const float inv = bcv;
        __half* out = pos + ((long)h * NN + n) * NN;
        out[tid] = __float2half_rn(e0 * inv);
        out[tid + 256] = __float2half_rn(e1 * inv);
        if (tid < 64) out[tid + 512] = __float2half_rn(e2 * inv);
        __syncthreads();
    }
}

// ---------------- fused one-pass attention (ldmatrix fragment loads) ------------
#define PB 36
#define FA_SMEM (6 * 64 * PB * 4)   // 55296 B

__global__ __launch_bounds__(256, 2) void fused_attn(
    const __half* __restrict__ qkh, const __half* __restrict__ qkl,
    const __half* __restrict__ v, const __half* __restrict__ pos,
    const float* __restrict__ gating, __half* __restrict__ o) {
    extern __shared__ unsigned smem[];
    const unsigned smA = (unsigned)__cvta_generic_to_shared(smem);
    unsigned* qs_h = smem;                 // [64][36] fp16x2 d-pairs
    unsigned* qs_l = qs_h + 64 * PB;
    unsigned* ks_h = qs_l + 64 * PB;       // [64 seq][36]
    unsigned* ks_l = ks_h + 64 * PB;
    unsigned* ps   = ks_l + 64 * PB;       // [64 qrow][36] fp16x2 seq-pairs
    unsigned* vt   = ps + 64 * PB;         // [64 d][36]  (V^T)
    const unsigned qhA = smA;
    const unsigned qlA = smA + 64 * PB * 4;
    const unsigned khA = smA + 2 * 64 * PB * 4;
    const unsigned klA = smA + 3 * 64 * PB * 4;
    const unsigned psA = smA + 4 * 64 * PB * 4;
    const unsigned vtA = smA + 5 * 64 * PB * 4;

    const int tid = threadIdx.x, warp = tid >> 5, lane = tid & 31;
    const int gp = lane >> 2, tg = lane & 3;
    const int wm = (warp & 3) * 16;
    const int wh = warp >> 2;
    const int n0 = blockIdx.x * 64;
    const int b = blockIdx.y >> 4, h = blockIdx.y & 15;
    const int lm15 = lane & 15, lh2 = (lane >> 4) & 1, lq = (lane >> 3) & 1, l7 = lane & 7;

    const __half* qhb = qkh + (long)b * NN * 2048 + (long)n0 * 2048 + h * 64;
    const __half* qlb = qkl + (long)b * NN * 2048 + (long)n0 * 2048 + h * 64;
    const __half* khb = qkh + (long)b * NN * 2048 + 1024 + h * 64;
    const __half* klb = qkl + (long)b * NN * 2048 + 1024 + h * 64;
    const __half* pbase = pos + ((long)h * NN + n0) * NN;

    // ---- load q tile (raw pre-split) ----
    {
        int idx = tid;
#pragma unroll
        for (int i = 0; i < 2; i++, idx += 256) {
            int r = idx >> 3, seg = idx & 7;
            *(uint4*)(qs_h + r * PB + seg * 4) = *(const uint4*)(qhb + (long)r * 2048 + seg * 8);
            *(uint4*)(qs_l + r * PB + seg * 4) = *(const uint4*)(qlb + (long)r * 2048 + seg * 8);
        }
    }

    float Oc[8][4], Op[8][4];
#pragma unroll
    for (int i = 0; i < 8; i++)
#pragma unroll
        for (int j = 0; j < 4; j++) { Oc[i][j] = 0.0f; Op[i][j] = 0.0f; }
    float l0 = 0.0f, l1 = 0.0f;
    const float scale = 0.125f;

    const int vd = tid & 63, vkg = tid >> 6;

    for (int m0 = 0; m0 < NN; m0 += 64) {
        __syncthreads();
        {
            int idx = tid;
#pragma unroll
            for (int i = 0; i < 2; i++, idx += 256) {
                int r = idx >> 3, seg = idx & 7;
                *(uint4*)(ks_h + r * PB + seg * 4) =
                    *(const uint4*)(khb + (long)(m0 + r) * 2048 + seg * 8);
                *(uint4*)(ks_l + r * PB + seg * 4) =
                    *(const uint4*)(klb + (long)(m0 + r) * 2048 + seg * 8);
                *(uint4*)(ps + r * PB + seg * 4) =
                    *(const uint4*)(pbase + (long)r * NN + m0 + seg * 8);
            }
            const __half* vp = v + ((long)b * NN + m0 + vkg * 16) * DD + h * 64 + vd;
            __half vv[16];
#pragma unroll
            for (int j = 0; j < 16; j++) vv[j] = vp[(long)j * DD];
#pragma unroll
            for (int i = 0; i < 8; i++)
                vt[vd * PB + vkg * 8 + i] = packh2(vv[2 * i], vv[2 * i + 1]);
        }
        __syncthreads();

        // ---- S = q @ k^T over warp's 16x32 slice (split-fp16, 3 terms) ----
        float p[4][4];
#pragma unroll
        for (int i = 0; i < 4; i++)
#pragma unroll
            for (int j = 0; j < 4; j++) p[i][j] = 0.0f;

#pragma unroll
        for (int kc = 0; kc < 4; kc++) {
            const unsigned qoff = ((wm + lm15) * PB + kc * 8 + lh2 * 4) << 2;
            unsigned ah0, ah1, ah2, ah3, al0, al1, al2, al3;
            ldsm_x4(ah0, ah1, ah2, ah3, qhA + qoff);
            ldsm_x4(al0, al1, al2, al3, qlA + qoff);
#pragma unroll
            for (int p2 = 0; p2 < 2; p2++) {
                const unsigned koff =
                    ((wh * 32 + p2 * 16 + lh2 * 8 + l7) * PB + kc * 8 + lq * 4) << 2;
                unsigned bh0, bh1, bh2, bh3, bl0, bl1, bl2, bl3;
                ldsm_x4(bh0, bh1, bh2, bh3, khA + koff);
                ldsm_x4(bl0, bl1, bl2, bl3, klA + koff);
                mma_fp16(p[2 * p2][0], p[2 * p2][1], p[2 * p2][2], p[2 * p2][3],
                         ah0, ah1, ah2, ah3, bh0, bh1);
                mma_fp16(p[2 * p2][0], p[2 * p2][1], p[2 * p2][2], p[2 * p2][3],
                         ah0, ah1, ah2, ah3, bl0, bl1);
                mma_fp16(p[2 * p2][0], p[2 * p2][1], p[2 * p2][2], p[2 * p2][3],
                         al0, al1, al2, al3, bh0, bh1);
                mma_fp16(p[2 * p2 + 1][0], p[2 * p2 + 1][1], p[2 * p2 + 1][2], p[2 * p2 + 1][3],
                         ah0, ah1, ah2, ah3, bh2, bh3);
                mma_fp16(p[2 * p2 + 1][0], p[2 * p2 + 1][1], p[2 * p2 + 1][2], p[2 * p2 + 1][3],
                         ah0, ah1, ah2, ah3, bl2, bl3);
                mma_fp16(p[2 * p2 + 1][0], p[2 * p2 + 1][1], p[2 * p2 + 1][2], p[2 * p2 + 1][3],
                         al0, al1, al2, al3, bh2, bh3);
            }
        }

        // ---- exp (no max-sub), row sums ----
#pragma unroll
        for (int na = 0; na < 4; na++) {
            p[na][0] = __expf(p[na][0] * scale);
            p[na][1] = __expf(p[na][1] * scale);
            p[na][2] = __expf(p[na][2] * scale);
            p[na][3] = __expf(p[na][3] * scale);
            l0 += p[na][0] + p[na][1];
            l1 += p[na][2] + p[na][3];
        }

        // ---- O_c += P@v, O_p += pos@v (plain fp16 k16) ----
#pragma unroll
        for (int s = 0; s < 2; s++) {
            unsigned Pa0 = pack2f(p[2 * s][0],     p[2 * s][1]);
            unsigned Pa1 = pack2f(p[2 * s][2],     p[2 * s][3]);
            unsigned Pa2 = pack2f(p[2 * s + 1][0], p[2 * s + 1][1]);
            unsigned Pa3 = pack2f(p[2 * s + 1][2], p[2 * s + 1][3]);

            unsigned pa0, pa1, pa2, pa3;
            const unsigned poff = ((wm + lm15) * PB + wh * 16 + s * 8 + lh2 * 4) << 2;
            ldsm_x4(pa0, pa1, pa2, pa3, psA + poff);
#pragma unroll
            for (int p2 = 0; p2 < 4; p2++) {
                const unsigned voff =
                    ((p2 * 16 + lh2 * 8 + l7) * PB + wh * 16 + s * 8 + lq * 4) << 2;
                unsigned b0a, b1a, b0b, b1b;
                ldsm_x4(b0a, b1a, b0b, b1b, vtA + voff);
                mma_fp16(Oc[2 * p2][0], Oc[2 * p2][1], Oc[2 * p2][2], Oc[2 * p2][3],
                         Pa0, Pa1, Pa2, Pa3, b0a, b1a);
                mma_fp16(Op[2 * p2][0], Op[2 * p2][1], Op[2 * p2][2], Op[2 * p2][3],
                         pa0, pa1, pa2, pa3, b0a, b1a);
                mma_fp16(Oc[2 * p2 + 1][0], Oc[2 * p2 + 1][1], Oc[2 * p2 + 1][2], Oc[2 * p2 + 1][3],
                         Pa0, Pa1, Pa2, Pa3, b0b, b1b);
                mma_fp16(Op[2 * p2 + 1][0], Op[2 * p2 + 1][1], Op[2 * p2 + 1][2], Op[2 * p2 + 1][3],
                         pa0, pa1, pa2, pa3, b0b, b1b);
            }
        }
    }

    // ---- reduce row-sums within tg group ----
    l0 += __shfl_xor_sync(~0u, l0, 1); l0 += __shfl_xor_sync(~0u, l0, 2);
    l1 += __shfl_xor_sync(~0u, l1, 1); l1 += __shfl_xor_sync(~0u, l1, 2);

    // ---- combine warp-half partials via smem scratch ----
    float* sOc = (float*)smem;          // [64][65]
    float* sOp = sOc + 64 * 65;
    float* slb = sOp + 64 * 65;
    __syncthreads();
    if (wh == 1) {
#pragma unroll
        for (int nv = 0; nv < 8; nv++) {
            const int base = (wm + gp) * 65 + nv * 8 + 2 * tg;
            sOc[base]              = Oc[nv][0];
            sOc[base + 1]          = Oc[nv][1];
            sOc[base + 8 * 65]     = Oc[nv][2];
            sOc[base + 8 * 65 + 1] = Oc[nv][3];
            sOp[base]              = Op[nv][0];
            sOp[base + 1]          = Op[nv][1];
            sOp[base + 8 * 65]     = Op[nv][2];
            sOp[base + 8 * 65 + 1] = Op[nv][3];
        }
        slb[wm + gp] = l0;
        slb[wm + gp + 8] = l1;
    }
    __syncthreads();
    if (wh == 0) {
        const float g = 1.0f / (1.0f + __expf(-gating[h]));
        const float og = 1.0f - g;
        const float lt0 = l0 + slb[wm + gp];
        const float lt1 = l1 + slb[wm + gp + 8];
        const float c0 = og / lt0, c1 = og / lt1;
        const long row = n0 + wm + gp;
        __half* dst0 = o + ((long)b * NN + row) * DD + h * 64;
#pragma unroll
        for (int nv = 0; nv < 8; nv++) {
            const int base = (wm + gp) * 65 + nv * 8 + 2 * tg;
            float oc0 = Oc[nv][0] + sOc[base];
            float oc1 = Oc[nv][1] + sOc[base + 1];
            float oc2 = Oc[nv][2] + sOc[base + 8 * 65];
            float oc3 = Oc[nv][3] + sOc[base + 8 * 65 + 1];
            float op0 = Op[nv][0] + sOp[base];
            float op1 = Op[nv][1] + sOp[base + 1];
            float op2 = Op[nv][2] + sOp[base + 8 * 65];
            float op3 = Op[nv][3] + sOp[base + 8 * 65 + 1];
            __half* dst = dst0 + nv * 8 + 2 * tg;
            *(unsigned*)dst = pack2f(c0 * oc0 + g * op0, c0 * oc1 + g * op1);
            *(unsigned*)(dst + 8L * DD) = pack2f(c1 * oc2 + g * op2, c1 * oc3 + g * op3);
        }
    }
}

// ---------------- launch ----------------
extern "C" void kernel_launch(void* const* d_in, const int* in_sizes, int n_in,
                              void* d_out, int out_size) {
    const float* x      = (const float*)d_in[0];
    const float* W_qk   = (const float*)d_in[1];
    const float* W_v    = (const float*)d_in[2];
    const float* W_proj = (const float*)d_in[3];
    const float* b_proj = (const float*)d_in[4];
    const float* W_pos  = (const float*)d_in[5];
    const float* b_pos  = (const float*)d_in[6];
    const float* gating = (const float*)d_in[7];
    const float* rel    = (const float*)d_in[8];
    float* out = (float*)d_out;

    __half *xh, *qkh, *qkl, *vh, *oh, *posh, *wtqk, *wtv, *wtp;
    cudaGetSymbolAddress((void**)&xh,   g_xh);
    cudaGetSymbolAddress((void**)&qkh,  g_qkh);
    cudaGetSymbolAddress((void**)&qkl,  g_qkl);
    cudaGetSymbolAddress((void**)&vh,   g_vh);
    cudaGetSymbolAddress((void**)&oh,   g_oh);
    cudaGetSymbolAddress((void**)&posh, g_posh);
    cudaGetSymbolAddress((void**)&wtqk, g_wtqk);
    cudaGetSymbolAddress((void**)&wtv,  g_wtv);
    cudaGetSymbolAddress((void**)&wtp,  g_wtp);

    cudaFuncSetAttribute(gemm_h<0, true>,  cudaFuncAttributeMaxDynamicSharedMemorySize, GS_SMEM);
    cudaFuncSetAttribute(gemm_h<1, false>, cudaFuncAttributeMaxDynamicSharedMemorySize, GS_SMEM);
    cudaFuncSetAttribute(gemm_h<2, false>, cudaFuncAttributeMaxDynamicSharedMemorySize, GS_SMEM);
    cudaFuncSetAttribute(fused_attn, cudaFuncAttributeMaxDynamicSharedMemorySize, FA_SMEM);

    const int M = BB * NN;  // 9216

    // prep: x -> fp16; W -> W^T fp16; pos softmax -> fp16
    cvt_half_k<<<(M * DD / 4 + 255) / 256, 256>>>(x, xh, M * DD);
    transpose_w<<<dim3(2 * DD / 32, DD / 32), dim3(32, 8)>>>(W_qk, wtqk, DD, 2 * DD);
    transpose_w<<<dim3(DD / 32, DD / 32), dim3(32, 8)>>>(W_v, wtv, DD, DD);
    transpose_w<<<dim3(DD / 32, DD / 32), dim3(32, 8)>>>(W_proj, wtp, DD, DD);
    pos_kernel<<<NN, 256>>>(rel, W_pos, b_pos, posh);

    // qk = x @ W_qk  (pre-split hi/lo fp16)
    gemm_h<2, false><<<dim3(2 * DD / 128, M / 128), 256, GS_SMEM>>>(
        xh, wtqk, nullptr, qkh, qkl, M, DD, 2 * DD);
    // v = x @ W_v  (fp16)
    gemm_h<1, false><<<dim3(DD / 128, M / 128), 256, GS_SMEM>>>(
        xh, wtv, nullptr, vh, nullptr, M, DD, DD);
    // fused one-pass attention -> o fp16
    fused_attn<<<dim3(NN / 64, BB * HH), 256, FA_SMEM>>>(qkh, qkl, vh, posh, gating, oh);
    // out = o @ W_proj + b_proj  (fp32 + bias)
    gemm_h<0, true><<<dim3(DD / 128, M / 128), 256, GS_SMEM>>>(
        oh, wtp, b_proj, out, nullptr, M, DD, DD);
}

// round 13
// speedup vs baseline: 2.2490x; 1.1217x over previous
#include <cuda_runtime.h>
#include <cuda_fp16.h>
#include <cstdint>

#define BB 16
#define NN 576
#define DD 1024
#define HH 16
#define HD 64

// ---------------- scratch (static device globals; no allocation) ----------------
__device__ __align__(16) __half g_xh[(long)BB * NN * DD];        // x fp16
__device__ __align__(16) __half g_qkh[(long)BB * NN * 2 * DD];   // qk fp16
__device__ __align__(16) __half g_vh[(long)BB * NN * DD];        // v fp16
__device__ __align__(16) __half g_oh[(long)BB * NN * DD];        // o fp16
__device__ __align__(16) __half g_posh[(long)HH * NN * NN];      // pos fp16
__device__ __align__(16) __half g_wtqk[(long)2 * DD * DD];       // W_qk^T fp16 [n][k]
__device__ __align__(16) __half g_wtv[(long)DD * DD];
__device__ __align__(16) __half g_wtp[(long)DD * DD];

// ---------------- helpers ------------------------------------------------------
__device__ __forceinline__ void mma_fp16(float& d0, float& d1, float& d2, float& d3,
                                         unsigned a0, unsigned a1, unsigned a2, unsigned a3,
                                         unsigned b0, unsigned b1) {
    asm volatile(
        "mma.sync.aligned.m16n8k16.row.col.f32.f16.f16.f32 "
        "{%0,%1,%2,%3}, {%4,%5,%6,%7}, {%8,%9}, {%0,%1,%2,%3};\n"
        : "+f"(d0), "+f"(d1), "+f"(d2), "+f"(d3)
        : "r"(a0), "r"(a1), "r"(a2), "r"(a3), "r"(b0), "r"(b1));
}

__device__ __forceinline__ void ldsm_x4(unsigned& r0, unsigned& r1, unsigned& r2,
                                        unsigned& r3, unsigned addr) {
    asm volatile("ldmatrix.sync.aligned.m8n8.x4.shared.b16 {%0,%1,%2,%3}, [%4];"
                 : "=r"(r0), "=r"(r1), "=r"(r2), "=r"(r3) : "r"(addr));
}

__device__ __forceinline__ unsigned packh2(__half x, __half y) {
    __half2 t;
    t.x = x; t.y = y;
    return *reinterpret_cast<unsigned*>(&t);
}

__device__ __forceinline__ unsigned pack2f(float x, float y) {
    return packh2(__float2half_rn(x), __float2half_rn(y));
}

// ---------------- prep: fp32 -> fp16 convert -----------------------------------
__global__ void cvt_half_k(const float* __restrict__ in, __half* __restrict__ out, int n) {
    int i = (blockIdx.x * 256 + threadIdx.x) * 4;
    if (i >= n) return;
    float4 a = *(const float4*)(in + i);
    __half2* o2 = (__half2*)(out + i);
    o2[0] = __floats2half2_rn(a.x, a.y);
    o2[1] = __floats2half2_rn(a.z, a.w);
}

// ---------------- prep: W [K][N] fp32 -> W^T [N][K] fp16 -----------------------
__global__ void transpose_w(const float* __restrict__ W, __half* __restrict__ Wt,
                            int K, int N) {
    __shared__ float t[32][33];
    const int k0 = blockIdx.y * 32, n0 = blockIdx.x * 32;
    const int tx = threadIdx.x, ty = threadIdx.y;
#pragma unroll
    for (int i = 0; i < 32; i += 8)
        t[ty + i][tx] = W[(long)(k0 + ty + i) * N + n0 + tx];
    __syncthreads();
#pragma unroll
    for (int i = 0; i < 32; i += 8)
        Wt[(long)(n0 + ty + i) * K + k0 + tx] = __float2half_rn(t[tx][ty + i]);
}

// ---------------- fp16 GEMM: C = A[M,K] @ Bt[N,K]^T ----------------------------
// 128x128 tile, K-chunk 32. 8 warps = 2m x 4n. ldmatrix fragment loads.
// CMODE: 0=fp32(+bias), 1=fp16.
#define GKP 20
#define G_WORDS (128 * GKP)
#define G_STG (2 * G_WORDS)
#define GS_SMEM (2 * G_STG * 4)               // 40960 B

template <int CMODE, bool BIAS>
__global__ __launch_bounds__(256, 2) void gemm_h(const __half* __restrict__ A,
                                                 const __half* __restrict__ Bt,
                                                 const float* __restrict__ bias,
                                                 void* __restrict__ C0,
                                                 int M, int K, int N) {
    extern __shared__ unsigned gsm[];
    const unsigned smA = (unsigned)__cvta_generic_to_shared(gsm);
    const int tid = threadIdx.x;
    const int warp = tid >> 5, lane = tid & 31;
    const int wm = (warp & 1) * 64, wn = (warp >> 1) * 32;
    const int gp = lane >> 2, tg = lane & 3;
    const int bm = blockIdx.y * 128, bn = blockIdx.x * 128;

    float acc[4][4][4];
#pragma unroll
    for (int i = 0; i < 4; i++)
#pragma unroll
        for (int j = 0; j < 4; j++)
#pragma unroll
            for (int r = 0; r < 4; r++) acc[i][j][r] = 0.0f;

    uint4 aS[2], bS[2];
    const __half* Ab = A + (long)bm * K;
    const __half* Bb = Bt + (long)bn * K;

    const int lm15 = lane & 15, lh = (lane >> 4) & 1, lq = (lane >> 3) & 1, l7 = lane & 7;

#define G_LOAD(k0)                                                              \
    {                                                                           \
        _Pragma("unroll") for (int i = 0; i < 2; i++) {                         \
            int idx = tid + 256 * i;                                            \
            int row = idx >> 2, seg = idx & 3;                                  \
            aS[i] = *(const uint4*)(Ab + (long)row * K + (k0) + seg * 8);       \
            bS[i] = *(const uint4*)(Bb + (long)row * K + (k0) + seg * 8);       \
        }                                                                       \
    }

#define G_STORE(s)                                                              \
    {                                                                           \
        unsigned* Ad = gsm + (s) * G_STG;                                       \
        unsigned* Bd = Ad + G_WORDS;                                            \
        _Pragma("unroll") for (int i = 0; i < 2; i++) {                         \
            int idx = tid + 256 * i;                                            \
            int row = idx >> 2, seg = idx & 3;                                  \
            *(uint4*)(Ad + row * GKP + seg * 4) = aS[i];                        \
            *(uint4*)(Bd + row * GKP + seg * 4) = bS[i];                        \
        }                                                                       \
    }

#define G_COMPUTE(s)                                                            \
    {                                                                           \
        const unsigned aBase = smA + (s) * G_STG * 4;                           \
        const unsigned bBase = aBase + G_WORDS * 4;                             \
        _Pragma("unroll") for (int st = 0; st < 2; st++) {                      \
            unsigned af[4][4];                                                  \
            _Pragma("unroll") for (int ma = 0; ma < 4; ma++)                    \
                ldsm_x4(af[ma][0], af[ma][1], af[ma][2], af[ma][3],             \
                        aBase + (((wm + ma * 16 + lm15) * GKP + st * 8 +        \
                                  lh * 4) << 2));                               \
            unsigned bf[4][2];                                                  \
            _Pragma("unroll") for (int p2 = 0; p2 < 2; p2++)                    \
                ldsm_x4(bf[2 * p2][0], bf[2 * p2][1], bf[2 * p2 + 1][0],        \
                        bf[2 * p2 + 1][1],                                      \
                        bBase + (((wn + p2 * 16 + lh * 8 + l7) * GKP +          \
                                  st * 8 + lq * 4) << 2));                      \
            _Pragma("unroll") for (int nb = 0; nb < 4; nb++)                    \
                _Pragma("unroll") for (int ma = 0; ma < 4; ma++)                \
                    mma_fp16(acc[ma][nb][0], acc[ma][nb][1], acc[ma][nb][2],    \
                             acc[ma][nb][3], af[ma][0], af[ma][1], af[ma][2],   \
                             af[ma][3], bf[nb][0], bf[nb][1]);                  \
        }                                                                       \
    }

    int s = 0;
    G_LOAD(0);
    G_STORE(0);
    __syncthreads();

    for (int k0 = 32; k0 < K; k0 += 32) {
        G_LOAD(k0);
        G_COMPUTE(s);
        G_STORE(s ^ 1);
        s ^= 1;
        __syncthreads();
    }
    G_COMPUTE(s);

#pragma unroll
    for (int ma = 0; ma < 4; ma++) {
        const long r0 = bm + wm + ma * 16 + gp;
        const long r1 = r0 + 8;
#pragma unroll
        for (int nb = 0; nb < 4; nb++) {
            const int col = bn + wn + nb * 8 + tg * 2;
            if (CMODE == 0) {
                float* C = (float*)C0;
                float2 v0 = make_float2(acc[ma][nb][0], acc[ma][nb][1]);
                float2 v1 = make_float2(acc[ma][nb][2], acc[ma][nb][3]);
                if (BIAS) {
                    const float bb0 = __ldg(bias + col), bb1 = __ldg(bias + col + 1);
                    v0.x += bb0; v0.y += bb1;
                    v1.x += bb0; v1.y += bb1;
                }
                *(float2*)(C + r0 * N + col) = v0;
                *(float2*)(C + r1 * N + col) = v1;
            } else {
                __half* C = (__half*)C0;
                *(unsigned*)(C + r0 * N + col) = pack2f(acc[ma][nb][0], acc[ma][nb][1]);
                *(unsigned*)(C + r1 * N + col) = pack2f(acc[ma][nb][2], acc[ma][nb][3]);
            }
        }
    }
#undef G_LOAD
#undef G_STORE
#undef G_COMPUTE
}

// ---------------- positional softmax -> fp16 (one block per row, loop heads) ---
__global__ __launch_bounds__(256) void pos_kernel(const float* __restrict__ rel,
                                                  const float* __restrict__ Wp,
                                                  const float* __restrict__ bp,
                                                  __half* __restrict__ pos) {
    const int n = blockIdx.x, tid = threadIdx.x;
    __shared__ float red[8];
    __shared__ float bcv;
    const float* r = rel + (long)n * NN * 3;

    const float r0x = r[tid * 3], r0y = r[tid * 3 + 1], r0z = r[tid * 3 + 2];
    const float r1x = r[(tid + 256) * 3], r1y = r[(tid + 256) * 3 + 1],
                r1z = r[(tid + 256) * 3 + 2];
    float r2x = 0, r2y = 0, r2z = 0;
    if (tid < 64) {
        r2x = r[(tid + 512) * 3]; r2y = r[(tid + 512) * 3 + 1];
        r2z = r[(tid + 512) * 3 + 2];
    }

    for (int h = 0; h < HH; h++) {
        const float w0 = Wp[h], w1 = Wp[HH + h], w2 = Wp[2 * HH + h], bb = bp[h];
        float s0 = r0x * w0 + r0y * w1 + r0z * w2 + bb;
        float s1 = r1x * w0 + r1y * w1 + r1z * w2 + bb;
        float s2 = (tid < 64) ? (r2x * w0 + r2y * w1 + r2z * w2 + bb) : -1e30f;

        float mx = fmaxf(fmaxf(s0, s1), s2);
#pragma unroll
        for (int o = 16; o; o >>= 1) mx = fmaxf(mx, __shfl_xor_sync(~0u, mx, o));
        if ((tid & 31) == 0) red[tid >> 5] = mx;
        __syncthreads();
        if (tid == 0) {
            float m = red[0];
            for (int i = 1; i < 8; i++) m = fmaxf(m, red[i]);
            bcv = m;
        }
        __syncthreads();
        mx = bcv;
        float e0 = expf(s0 - mx), e1 = expf(s1 - mx);
        float e2 = (tid < 64) ? expf(s2 - mx) : 0.0f;
        float sum = e0 + e1 + e2;
#pragma unroll
        for (int o = 16; o; o >>= 1) sum += __shfl_xor_sync(~0u, sum, o);
        if ((tid & 31) == 0) red[tid >> 5] = sum;
        __syncthreads();
        if (tid == 0) {
            float s = 0.f;
            for (int i = 0; i < 8; i++) s += red[i];
            bcv = 1.0f / s;
        }
        __syncthreads();
        const float inv = bcv;
        __half* out = pos + ((long)h * NN + n) * NN;
        out[tid] = __float2half_rn(e0 * inv);
        out[tid + 256] = __float2half_rn(e1 * inv);
        if (tid < 64) out[tid + 512] = __float2half_rn(e2 * inv);
        __syncthreads();
    }
}

// ---------------- fused one-pass attention (plain fp16 S + PV) ------------------
#define PB 36
#define FA_SMEM (4 * 64 * PB * 4)   // 36864 B

__global__ __launch_bounds__(256, 2) void fused_attn(
    const __half* __restrict__ qk, const __half* __restrict__ v,
    const __half* __restrict__ pos, const float* __restrict__ gating,
    __half* __restrict__ o) {
    extern __shared__ unsigned smem[];
    const unsigned smA = (unsigned)__cvta_generic_to_shared(smem);
    unsigned* qs = smem;                   // [64][36] fp16x2 d-pairs
    unsigned* ks = qs + 64 * PB;           // [64 seq][36]
    unsigned* ps = ks + 64 * PB;           // [64 qrow][36] fp16x2 seq-pairs
    unsigned* vt = ps + 64 * PB;           // [64 d][36]  (V^T)
    const unsigned qA = smA;
    const unsigned kA = smA + 64 * PB * 4;
    const unsigned pA = smA + 2 * 64 * PB * 4;
    const unsigned vA = smA + 3 * 64 * PB * 4;

    const int tid = threadIdx.x, warp = tid >> 5, lane = tid & 31;
    const int gp = lane >> 2, tg = lane & 3;
    const int wm = (warp & 3) * 16;
    const int wh = warp >> 2;
    const int n0 = blockIdx.x * 64;
    const int b = blockIdx.y >> 4, h = blockIdx.y & 15;
    const int lm15 = lane & 15, lh2 = (lane >> 4) & 1, lq = (lane >> 3) & 1, l7 = lane & 7;

    const __half* qb = qk + (long)b * NN * 2048 + (long)n0 * 2048 + h * 64;
    const __half* kb = qk + (long)b * NN * 2048 + 1024 + h * 64;
    const __half* pbase = pos + ((long)h * NN + n0) * NN;

    // ---- load q tile ----
    {
        int idx = tid;
#pragma unroll
        for (int i = 0; i < 2; i++, idx += 256) {
            int r = idx >> 3, seg = idx & 7;
            *(uint4*)(qs + r * PB + seg * 4) = *(const uint4*)(qb + (long)r * 2048 + seg * 8);
        }
    }

    float Oc[8][4], Op[8][4];
#pragma unroll
    for (int i = 0; i < 8; i++)
#pragma unroll
        for (int j = 0; j < 4; j++) { Oc[i][j] = 0.0f; Op[i][j] = 0.0f; }
    float l0 = 0.0f, l1 = 0.0f;
    const float scale = 0.125f;

    const int vd = tid & 63, vkg = tid >> 6;

    for (int m0 = 0; m0 < NN; m0 += 64) {
        __syncthreads();
        {
            int idx = tid;
#pragma unroll
            for (int i = 0; i < 2; i++, idx += 256) {
                int r = idx >> 3, seg = idx & 7;
                *(uint4*)(ks + r * PB + seg * 4) =
                    *(const uint4*)(kb + (long)(m0 + r) * 2048 + seg * 8);
                *(uint4*)(ps + r * PB + seg * 4) =
                    *(const uint4*)(pbase + (long)r * NN + m0 + seg * 8);
            }
            const __half* vp = v + ((long)b * NN + m0 + vkg * 16) * DD + h * 64 + vd;
            __half vv[16];
#pragma unroll
            for (int j = 0; j < 16; j++) vv[j] = vp[(long)j * DD];
#pragma unroll
            for (int i = 0; i < 8; i++)
                vt[vd * PB + vkg * 8 + i] = packh2(vv[2 * i], vv[2 * i + 1]);
        }
        __syncthreads();

        // ---- S = q @ k^T over warp's 16x32 slice (plain fp16) ----
        float p[4][4];
#pragma unroll
        for (int i = 0; i < 4; i++)
#pragma unroll
            for (int j = 0; j < 4; j++) p[i][j] = 0.0f;

#pragma unroll
        for (int kc = 0; kc < 4; kc++) {
            const unsigned qoff = ((wm + lm15) * PB + kc * 8 + lh2 * 4) << 2;
            unsigned a0, a1, a2, a3;
            ldsm_x4(a0, a1, a2, a3, qA + qoff);
#pragma unroll
            for (int p2 = 0; p2 < 2; p2++) {
                const unsigned koff =
                    ((wh * 32 + p2 * 16 + lh2 * 8 + l7) * PB + kc * 8 + lq * 4) << 2;
                unsigned b0, b1, b2, b3;
                ldsm_x4(b0, b1, b2, b3, kA + koff);
                mma_fp16(p[2 * p2][0], p[2 * p2][1], p[2 * p2][2], p[2 * p2][3],
                         a0, a1, a2, a3, b0, b1);
                mma_fp16(p[2 * p2 + 1][0], p[2 * p2 + 1][1], p[2 * p2 + 1][2], p[2 * p2 + 1][3],
                         a0, a1, a2, a3, b2, b3);
            }
        }

        // ---- exp (no max-sub), row sums ----
#pragma unroll
        for (int na = 0; na < 4; na++) {
            p[na][0] = __expf(p[na][0] * scale);
            p[na][1] = __expf(p[na][1] * scale);
            p[na][2] = __expf(p[na][2] * scale);
            p[na][3] = __expf(p[na][3] * scale);
            l0 += p[na][0] + p[na][1];
            l1 += p[na][2] + p[na][3];
        }

        // ---- O_c += P@v, O_p += pos@v (plain fp16 k16) ----
#pragma unroll
        for (int s = 0; s < 2; s++) {
            unsigned Pa0 = pack2f(p[2 * s][0],     p[2 * s][1]);
            unsigned Pa1 = pack2f(p[2 * s][2],     p[2 * s][3]);
            unsigned Pa2 = pack2f(p[2 * s + 1][0], p[2 * s + 1][1]);
            unsigned Pa3 = pack2f(p[2 * s + 1][2], p[2 * s + 1][3]);

            unsigned pa0, pa1, pa2, pa3;
            const unsigned poff = ((wm + lm15) * PB + wh * 16 + s * 8 + lh2 * 4) << 2;
            ldsm_x4(pa0, pa1, pa2, pa3, pA + poff);
#pragma unroll
            for (int p2 = 0; p2 < 4; p2++) {
                const unsigned voff =
                    ((p2 * 16 + lh2 * 8 + l7) * PB + wh * 16 + s * 8 + lq * 4) << 2;
                unsigned b0a, b1a, b0b, b1b;
                ldsm_x4(b0a, b1a, b0b, b1b, vA + voff);
                mma_fp16(Oc[2 * p2][0], Oc[2 * p2][1], Oc[2 * p2][2], Oc[2 * p2][3],
                         Pa0, Pa1, Pa2, Pa3, b0a, b1a);
                mma_fp16(Op[2 * p2][0], Op[2 * p2][1], Op[2 * p2][2], Op[2 * p2][3],
                         pa0, pa1, pa2, pa3, b0a, b1a);
                mma_fp16(Oc[2 * p2 + 1][0], Oc[2 * p2 + 1][1], Oc[2 * p2 + 1][2], Oc[2 * p2 + 1][3],
                         Pa0, Pa1, Pa2, Pa3, b0b, b1b);
                mma_fp16(Op[2 * p2 + 1][0], Op[2 * p2 + 1][1], Op[2 * p2 + 1][2], Op[2 * p2 + 1][3],
                         pa0, pa1, pa2, pa3, b0b, b1b);
            }
        }
    }

    // ---- reduce row-sums within tg group ----
    l0 += __shfl_xor_sync(~0u, l0, 1); l0 += __shfl_xor_sync(~0u, l0, 2);
    l1 += __shfl_xor_sync(~0u, l1, 1); l1 += __shfl_xor_sync(~0u, l1, 2);

    // ---- combine warp-half partials via smem scratch ----
    float* sOc = (float*)smem;          // [64][65]
    float* sOp = sOc + 64 * 65;
    float* slb = sOp + 64 * 65;
    __syncthreads();
    if (wh == 1) {
#pragma unroll
        for (int nv = 0; nv < 8; nv++) {
            const int base = (wm + gp) * 65 + nv * 8 + 2 * tg;
            sOc[base]              = Oc[nv][0];
            sOc[base + 1]          = Oc[nv][1];
            sOc[base + 8 * 65]     = Oc[nv][2];
            sOc[base + 8 * 65 + 1] = Oc[nv][3];
            sOp[base]              = Op[nv][0];
            sOp[base + 1]          = Op[nv][1];
            sOp[base + 8 * 65]     = Op[nv][2];
            sOp[base + 8 * 65 + 1] = Op[nv][3];
        }
        slb[wm + gp] = l0;
        slb[wm + gp + 8] = l1;
    }
    __syncthreads();
    if (wh == 0) {
        const float g = 1.0f / (1.0f + __expf(-gating[h]));
        const float og = 1.0f - g;
        const float lt0 = l0 + slb[wm + gp];
        const float lt1 = l1 + slb[wm + gp + 8];
        const float c0 = og / lt0, c1 = og / lt1;
        const long row = n0 + wm + gp;
        __half* dst0 = o + ((long)b * NN + row) * DD + h * 64;
#pragma unroll
        for (int nv = 0; nv < 8; nv++) {
            const int base = (wm + gp) * 65 + nv * 8 + 2 * tg;
            float oc0 = Oc[nv][0] + sOc[base];
            float oc1 = Oc[nv][1] + sOc[base + 1];
            float oc2 = Oc[nv][2] + sOc[base + 8 * 65];
            float oc3 = Oc[nv][3] + sOc[base + 8 * 65 + 1];
            float op0 = Op[nv][0] + sOp[base];
            float op1 = Op[nv][1] + sOp[base + 1];
            float op2 = Op[nv][2] + sOp[base + 8 * 65];
            float op3 = Op[nv][3] + sOp[base + 8 * 65 + 1];
            __half* dst = dst0 + nv * 8 + 2 * tg;
            *(unsigned*)dst = pack2f(c0 * oc0 + g * op0, c0 * oc1 + g * op1);
            *(unsigned*)(dst + 8L * DD) = pack2f(c1 * oc2 + g * op2, c1 * oc3 + g * op3);
        }
    }
}

// ---------------- launch ----------------
extern "C" void kernel_launch(void* const* d_in, const int* in_sizes, int n_in,
                              void* d_out, int out_size) {
    const float* x      = (const float*)d_in[0];
    const float* W_qk   = (const float*)d_in[1];
    const float* W_v    = (const float*)d_in[2];
    const float* W_proj = (const float*)d_in[3];
    const float* b_proj = (const float*)d_in[4];
    const float* W_pos  = (const float*)d_in[5];
    const float* b_pos  = (const float*)d_in[6];
    const float* gating = (const float*)d_in[7];
    const float* rel    = (const float*)d_in[8];
    float* out = (float*)d_out;

    __half *xh, *qkh, *vh, *oh, *posh, *wtqk, *wtv, *wtp;
    cudaGetSymbolAddress((void**)&xh,   g_xh);
    cudaGetSymbolAddress((void**)&qkh,  g_qkh);
    cudaGetSymbolAddress((void**)&vh,   g_vh);
    cudaGetSymbolAddress((void**)&oh,   g_oh);
    cudaGetSymbolAddress((void**)&posh, g_posh);
    cudaGetSymbolAddress((void**)&wtqk, g_wtqk);
    cudaGetSymbolAddress((void**)&wtv,  g_wtv);
    cudaGetSymbolAddress((void**)&wtp,  g_wtp);

    cudaFuncSetAttribute(gemm_h<0, true>,  cudaFuncAttributeMaxDynamicSharedMemorySize, GS_SMEM);
    cudaFuncSetAttribute(gemm_h<1, false>, cudaFuncAttributeMaxDynamicSharedMemorySize, GS_SMEM);
    cudaFuncSetAttribute(fused_attn, cudaFuncAttributeMaxDynamicSharedMemorySize, FA_SMEM);

    const int M = BB * NN;  // 9216

    // prep: x -> fp16; W -> W^T fp16; pos softmax -> fp16
    cvt_half_k<<<(M * DD / 4 + 255) / 256, 256>>>(x, xh, M * DD);
    transpose_w<<<dim3(2 * DD / 32, DD / 32), dim3(32, 8)>>>(W_qk, wtqk, DD, 2 * DD);
    transpose_w<<<dim3(DD / 32, DD / 32), dim3(32, 8)>>>(W_v, wtv, DD, DD);
    transpose_w<<<dim3(DD / 32, DD / 32), dim3(32, 8)>>>(W_proj, wtp, DD, DD);
    pos_kernel<<<NN, 256>>>(rel, W_pos, b_pos, posh);

    // qk = x @ W_qk  (plain fp16)
    gemm_h<1, false><<<dim3(2 * DD / 128, M / 128), 256, GS_SMEM>>>(
        xh, wtqk, nullptr, qkh, M, DD, 2 * DD);
    // v = x @ W_v  (fp16)
    gemm_h<1, false><<<dim3(DD / 128, M / 128), 256, GS_SMEM>>>(
        xh, wtv, nullptr, vh, M, DD, DD);
    // fused one-pass attention -> o fp16
    fused_attn<<<dim3(NN / 64, BB * HH), 256, FA_SMEM>>>(qkh, vh, posh, gating, oh);
    // out = o @ W_proj + b_proj  (fp32 + bias)
    gemm_h<0, true><<<dim3(DD / 128, M / 128), 256, GS_SMEM>>>(
        oh, wtp, b_proj, out, M, DD, DD);
}